// round 11
// baseline (speedup 1.0000x reference)
#include <cuda_runtime.h>
#include <cuda_bf16.h>
#include <cstdint>
#include <math.h>

// Problem constants
#define BB 4
#define SS 1024
#define DD 1024
#define HH 16
#define HD 64
#define MLPD 4096
#define MODW 6144   // 6*D
#define LN_EPS 1e-5f

typedef __nv_bfloat16 bf16;
typedef __nv_bfloat162 bf162;

// ---------------- scratch (no allocs allowed) ----------------
__device__ float g_mod[BB * MODW];
__device__ bf16  g_xm[(size_t)BB * SS * DD];
__device__ bf16  g_qkv[(size_t)BB * SS * 3 * DD];        // bf16; q,k roped in place
__device__ bf16  g_attn[(size_t)BB * SS * DD];
__device__ float g_x1[(size_t)BB * SS * DD];
__device__ bf16  g_h[(size_t)BB * SS * MLPD];
__device__ bf16  g_vt[(size_t)BB * HH * HD * SS];        // V^T [b][h][d][s]
// transposed bf16 weights [N][K]
__device__ bf16 g_wqkv_t[(size_t)3 * DD * DD];
__device__ bf16 g_wout_t[(size_t)DD * DD];
__device__ bf16 g_w1_t[(size_t)MLPD * DD];
__device__ bf16 g_w2_t[(size_t)DD * MLPD];

// ---------------- helpers ----------------
__device__ __forceinline__ unsigned smaddr(const void* p) {
    return (unsigned)__cvta_generic_to_shared(p);
}
__device__ __forceinline__ void ldsm_x4(unsigned& r0, unsigned& r1, unsigned& r2,
                                        unsigned& r3, unsigned a) {
    asm volatile("ldmatrix.sync.aligned.m8n8.x4.shared.b16 {%0,%1,%2,%3},[%4];"
                 : "=r"(r0), "=r"(r1), "=r"(r2), "=r"(r3) : "r"(a));
}
__device__ __forceinline__ void ldsm_x2(unsigned& r0, unsigned& r1, unsigned a) {
    asm volatile("ldmatrix.sync.aligned.m8n8.x2.shared.b16 {%0,%1},[%2];"
                 : "=r"(r0), "=r"(r1) : "r"(a));
}
__device__ __forceinline__ void mma_bf16(float c[4], unsigned a0, unsigned a1,
                                         unsigned a2, unsigned a3,
                                         unsigned b0, unsigned b1) {
    asm volatile("mma.sync.aligned.m16n8k16.row.col.f32.bf16.bf16.f32 "
                 "{%0,%1,%2,%3}, {%4,%5,%6,%7}, {%8,%9}, {%0,%1,%2,%3};"
                 : "+f"(c[0]), "+f"(c[1]), "+f"(c[2]), "+f"(c[3])
                 : "r"(a0), "r"(a1), "r"(a2), "r"(a3), "r"(b0), "r"(b1));
}
__device__ __forceinline__ void cp16(void* s, const void* g) {
    asm volatile("cp.async.cg.shared.global [%0], [%1], 16;"
                 :: "r"(smaddr(s)), "l"(g));
}
__device__ __forceinline__ unsigned f2bf(float x, float y) {
    bf162 t = __floats2bfloat162_rn(x, y);
    return *(unsigned*)&t;
}

// ---------------- merged weight transpose + bf16 convert ----------------------
__global__ void wtrans_all_kernel(const float* __restrict__ s0, const float* __restrict__ s1,
                                  const float* __restrict__ s2, const float* __restrict__ s3,
                                  bf16* __restrict__ d0, bf16* __restrict__ d1,
                                  bf16* __restrict__ d2, bf16* __restrict__ d3) {
    __shared__ float t[32][33];
    int tb = blockIdx.x;
    const float* src; bf16* dst; int K, N;
    if (tb < 3072)      { src = s0; dst = d0; K = 1024; N = 3072; }
    else if (tb < 4096) { tb -= 3072; src = s1; dst = d1; K = 1024; N = 1024; }
    else if (tb < 8192) { tb -= 4096; src = s2; dst = d2; K = 1024; N = 4096; }
    else                { tb -= 8192; src = s3; dst = d3; K = 4096; N = 1024; }
    int ntn = N >> 5;
    int k0 = (tb / ntn) * 32, n0 = (tb % ntn) * 32;
    int tx = threadIdx.x, ty = threadIdx.y;
#pragma unroll
    for (int j = ty; j < 32; j += 8)
        t[j][tx] = src[(size_t)(k0 + j) * N + n0 + tx];
    __syncthreads();
#pragma unroll
    for (int j = ty; j < 32; j += 8)
        dst[(size_t)(n0 + j) * K + k0 + tx] = __float2bfloat16_rn(t[tx][j]);
}

// ---------------- adaLN modulation ----------------
__global__ void mod_kernel(const float* __restrict__ c, const float* __restrict__ w,
                           const float* __restrict__ bias, float* __restrict__ mod) {
    int n = blockIdx.x * blockDim.x + threadIdx.x;
    if (n >= BB * MODW) return;
    int b = n / MODW;
    int col = n - b * MODW;
    float acc = bias[col];
    const float* cb = c + b * 128;
#pragma unroll 8
    for (int k = 0; k < 128; k++) acc = fmaf(cb[k], w[(size_t)k * MODW + col], acc);
    mod[n] = acc;
}

// ---------------- fused LayerNorm + modulate (vectorized, bf16 out) -----------
__global__ __launch_bounds__(256)
void ln_mod_kernel(const float* __restrict__ x, const float* __restrict__ w,
                   const float* __restrict__ mod, int shiftSeg, int scaleSeg,
                   bf16* __restrict__ out) {
    __shared__ float r1[8], r2[8];
    int row = blockIdx.x;
    int b = row >> 10;
    int tid = threadIdx.x, lane = tid & 31, wrp = tid >> 5;
    float4 v = ((const float4*)(x + (size_t)row * DD))[tid];
    float s = v.x + v.y + v.z + v.w;
    float ss = v.x * v.x + v.y * v.y + v.z * v.z + v.w * v.w;
#pragma unroll
    for (int o = 16; o > 0; o >>= 1) {
        s  += __shfl_xor_sync(0xffffffffu, s, o);
        ss += __shfl_xor_sync(0xffffffffu, ss, o);
    }
    if (lane == 0) { r1[wrp] = s; r2[wrp] = ss; }
    __syncthreads();
    if (wrp == 0) {
        float a = (lane < 8) ? r1[lane] : 0.f;
        float c2 = (lane < 8) ? r2[lane] : 0.f;
#pragma unroll
        for (int o = 4; o > 0; o >>= 1) {
            a  += __shfl_xor_sync(0xffffffffu, a, o);
            c2 += __shfl_xor_sync(0xffffffffu, c2, o);
        }
        if (lane == 0) { r1[0] = a; r2[0] = c2; }
    }
    __syncthreads();
    float mu = r1[0] * (1.0f / DD);
    float var = r2[0] * (1.0f / DD) - mu * mu;
    float rstd = rsqrtf(var + LN_EPS);
    float4 wv = ((const float4*)w)[tid];
    float4 sh = ((const float4*)(mod + (size_t)b * MODW + shiftSeg * DD))[tid];
    float4 sc = ((const float4*)(mod + (size_t)b * MODW + scaleSeg * DD))[tid];
    float y0 = fmaf((v.x - mu) * rstd * wv.x, 1.0f + sc.x, sh.x);
    float y1 = fmaf((v.y - mu) * rstd * wv.y, 1.0f + sc.y, sh.y);
    float y2 = fmaf((v.z - mu) * rstd * wv.z, 1.0f + sc.z, sh.z);
    float y3 = fmaf((v.w - mu) * rstd * wv.w, 1.0f + sc.w, sh.w);
    uint2 o2 = make_uint2(f2bf(y0, y1), f2bf(y2, y3));
    *(uint2*)(out + (size_t)row * DD + tid * 4) = o2;
}

__device__ __forceinline__ float gelu_tanh(float x) {
    float x3 = x * x * x;
    return 0.5f * x * (1.0f + tanhf(0.7978845608028654f * (x + 0.044715f * x3)));
}

// ---------------- bf16 tensor-core GEMM: 4 warps 64x64, k-stage 64, 3-ring ----
// CTA 128x128, 128 threads, K-stage 64, 3-stage cp.async ring.
// As[m][k], Bs[n][k], stride 72 halves (conflict-free ldmatrix).
#define TG_STRIDE 72
#define TG_HBUF (128 * TG_STRIDE)
#define TG_STAGE (2 * TG_HBUF)
#define TG_BYTES (3 * TG_STAGE * 2)              // 110592 B

template<int EPI>
__global__ __launch_bounds__(128, 2)
void tgemm(const bf16* __restrict__ A, const bf16* __restrict__ Bt,
           const float* __restrict__ bias, const float* __restrict__ resid,
           const float* __restrict__ mod, int modOff,
           void* __restrict__ Cv, int M, int N, int K) {
    extern __shared__ bf16 smh[];
    const int tid = threadIdx.x;
    const int lane = tid & 31, wid = tid >> 5;
    const int gid = lane >> 2, tig = lane & 3;
    const int bx = blockIdx.x, by = blockIdx.y;
    const int m0w = (wid & 1) * 64;
    const int n0w = (wid >> 1) * 64;

    const int aRowOff = (lane & 15) * TG_STRIDE + 8 * (lane >> 4);
    const int bRowOff = (lane & 7) * TG_STRIDE + 8 * ((lane >> 3) & 1);

    const bf16* Ag = A + (size_t)(by * 128) * K;
    const bf16* Bg = Bt + (size_t)(bx * 128) * K;

    float acc[4][8][4];
#pragma unroll
    for (int i = 0; i < 4; i++)
#pragma unroll
        for (int j = 0; j < 8; j++)
#pragma unroll
            for (int r = 0; r < 4; r++) acc[i][j][r] = 0.f;

    const int NS = K >> 6;

    auto issue = [&](int ks) {
        bf16* As = smh + (ks % 3) * TG_STAGE;
        bf16* Bs = As + TG_HBUF;
#pragma unroll
        for (int e = 0; e < 8; e++) {
            int idx = tid + e * 128;            // [0,1024)
            int row = idx >> 3, q = idx & 7;
            cp16(&As[row * TG_STRIDE + q * 8], Ag + (size_t)row * K + ks * 64 + q * 8);
        }
#pragma unroll
        for (int e = 0; e < 8; e++) {
            int idx = tid + e * 128;
            int row = idx >> 3, q = idx & 7;
            cp16(&Bs[row * TG_STRIDE + q * 8], Bg + (size_t)row * K + ks * 64 + q * 8);
        }
        asm volatile("cp.async.commit_group;");
    };

    issue(0); issue(1);

    for (int ks = 0; ks < NS; ks++) {
        if (ks + 1 < NS) asm volatile("cp.async.wait_group 1;" ::: "memory");
        else             asm volatile("cp.async.wait_group 0;" ::: "memory");
        __syncthreads();
        if (ks + 2 < NS) issue(ks + 2);
        const bf16* As = smh + (ks % 3) * TG_STAGE;
        const bf16* Bs = As + TG_HBUF;

        unsigned af[2][4][4], bfv[2][8][2];
        // load fragments for sub-step 0
#pragma unroll
        for (int mt = 0; mt < 4; mt++)
            ldsm_x4(af[0][mt][0], af[0][mt][1], af[0][mt][2], af[0][mt][3],
                    smaddr(&As[(m0w + mt * 16) * TG_STRIDE + aRowOff]));
#pragma unroll
        for (int nt = 0; nt < 8; nt++)
            ldsm_x2(bfv[0][nt][0], bfv[0][nt][1],
                    smaddr(&Bs[(n0w + nt * 8) * TG_STRIDE + bRowOff]));

#pragma unroll
        for (int sub = 0; sub < 4; sub++) {
            int cur = sub & 1;
            if (sub < 3) {
                int nxt = (sub + 1) & 1;
                int K0 = (sub + 1) * 16;
#pragma unroll
                for (int mt = 0; mt < 4; mt++)
                    ldsm_x4(af[nxt][mt][0], af[nxt][mt][1], af[nxt][mt][2], af[nxt][mt][3],
                            smaddr(&As[(m0w + mt * 16) * TG_STRIDE + aRowOff + K0]));
#pragma unroll
                for (int nt = 0; nt < 8; nt++)
                    ldsm_x2(bfv[nxt][nt][0], bfv[nxt][nt][1],
                            smaddr(&Bs[(n0w + nt * 8) * TG_STRIDE + bRowOff + K0]));
            }
#pragma unroll
            for (int mt = 0; mt < 4; mt++)
#pragma unroll
                for (int nt = 0; nt < 8; nt++)
                    mma_bf16(acc[mt][nt], af[cur][mt][0], af[cur][mt][1],
                             af[cur][mt][2], af[cur][mt][3],
                             bfv[cur][nt][0], bfv[cur][nt][1]);
        }
    }

    // ---- epilogue ----
#pragma unroll
    for (int mt = 0; mt < 4; mt++) {
#pragma unroll
        for (int half = 0; half < 2; half++) {
            int row = by * 128 + m0w + mt * 16 + gid + 8 * half;
            size_t rowBase = (size_t)row * N;
#pragma unroll
            for (int nt = 0; nt < 8; nt++) {
                int col = bx * 128 + n0w + nt * 8 + 2 * tig;
                float v0 = acc[mt][nt][2 * half];
                float v1 = acc[mt][nt][2 * half + 1];
                if (EPI == 1) {
                    v0 = gelu_tanh(v0 + bias[col]);
                    v1 = gelu_tanh(v1 + bias[col + 1]);
                    *(unsigned*)&((bf16*)Cv)[rowBase + col] = f2bf(v0, v1);
                } else if (EPI == 2) {
                    if (bias) { v0 += bias[col]; v1 += bias[col + 1]; }
                    size_t mb = (size_t)(row >> 10) * MODW + modOff + col;
                    float g0 = mod[mb], g1 = mod[mb + 1];
                    float2 rr = *(const float2*)&resid[rowBase + col];
                    *(float2*)&((float*)Cv)[rowBase + col] =
                        make_float2(fmaf(g0, v0, rr.x), fmaf(g1, v1, rr.y));
                } else {
                    *(unsigned*)&((bf16*)Cv)[rowBase + col] = f2bf(v0, v1);
                }
            }
        }
    }
}

// ---------------- RoPE in place on bf16 qkv; q scaled by 1/8 ------------------
__global__ void rope_bf16_kernel(bf16* __restrict__ qkv, const float* __restrict__ cosb,
                                 const float* __restrict__ sinb) {
    int id = blockIdx.x * blockDim.x + threadIdx.x;   // B*S*2*H*32
    if (id >= BB * SS * 2 * HH * 32) return;
    int e = id & 31;
    int h = (id >> 5) & 15;
    int sel = (id >> 9) & 1;        // 0 = q, 1 = k
    int bs = id >> 10;
    int s = bs & (SS - 1);
    size_t base = (size_t)bs * 3072 + (size_t)sel * 1024 + h * 64;
    float t1 = __bfloat162float(qkv[base + e]);
    float t2 = __bfloat162float(qkv[base + e + 32]);
    float cv = cosb[s * 32 + e];
    float sv = sinb[s * 32 + e];
    float scale = sel ? 1.0f : 0.125f;
    qkv[base + e]      = __float2bfloat16_rn((t1 * cv - t2 * sv) * scale);
    qkv[base + e + 32] = __float2bfloat16_rn((t2 * cv + t1 * sv) * scale);
}

// ---------------- V transpose: bf16 qkv v-part -> vt[b][h][d][s] --------------
__global__ void vtrans_kernel(const bf16* __restrict__ qkv, bf16* __restrict__ vt) {
    __shared__ bf16 t[32][34];
    int b = blockIdx.z;
    int s0 = blockIdx.x * 32, hd0 = blockIdx.y * 32;
    int tx = threadIdx.x, ty = threadIdx.y;
#pragma unroll
    for (int j = ty; j < 32; j += 8)
        t[j][tx] = qkv[(size_t)(b * 1024 + s0 + j) * 3072 + 2048 + hd0 + tx];
    __syncthreads();
#pragma unroll
    for (int j = ty; j < 32; j += 8)
        vt[(size_t)(b * 1024 + hd0 + j) * 1024 + s0 + tx] = t[tx][j];
}

// ---------------- attention: flash, bf16 mma, ldmatrix, cp.async K/V ----------
#define AT_STRIDE 72
#define AT_HBUF (64 * AT_STRIDE)
#define AT_SMEM_BYTES (6 * AT_HBUF * 2)          // 55296 B

__global__ __launch_bounds__(128, 3)
void attn_mma_kernel(const bf16* __restrict__ qkv, const bf16* __restrict__ vt,
                     bf16* __restrict__ out) {
    extern __shared__ bf16 smh[];
    bf16* Qs = smh;
    bf16* Ps = Qs + AT_HBUF;
    bf16* Kb[2] = { Ps + AT_HBUF, Ps + 3 * AT_HBUF };
    bf16* Vb[2] = { Ps + 2 * AT_HBUF, Ps + 4 * AT_HBUF };
    int bh = blockIdx.x;
    int b = bh >> 4, h = bh & 15;
    size_t bS = (size_t)b * SS;
    int q0 = blockIdx.y * 64;
    int tid = threadIdx.x, w = tid >> 5, lane = tid & 31;
    int gid = lane >> 2, tig = lane & 3;
    const int aRowOff = (lane & 15) * AT_STRIDE + 8 * (lane >> 4);
    const int bRowOff = (lane & 7) * AT_STRIDE + 8 * ((lane >> 3) & 1);

    const bf16* vbase = vt + ((size_t)(b * 1024 + h * 64)) * 1024;

    auto issue_tile = [&](int kt) {
        int kb0 = kt * 64;
        bf16* Ks = Kb[kt & 1];
        bf16* Vs = Vb[kt & 1];
#pragma unroll
        for (int e = 0; e < 4; e++) {
            int idx = tid + e * 128;            // [0,512)
            int r = idx >> 3, q = idx & 7;
            cp16(&Ks[r * AT_STRIDE + q * 8],
                 qkv + (bS + kb0 + r) * 3072 + 1024 + h * 64 + q * 8);
            cp16(&Vs[r * AT_STRIDE + q * 8],
                 vbase + (size_t)r * 1024 + kb0 + q * 8);
        }
        asm volatile("cp.async.commit_group;");
    };

    issue_tile(0);

    // stage Q (already roped + scaled)
    {
        int q = tid >> 1, d0 = (tid & 1) * 32;
        const uint4* src = (const uint4*)(qkv + (bS + q0 + q) * 3072 + h * 64 + d0);
        uint4* dst = (uint4*)&Qs[q * AT_STRIDE + d0];
        dst[0] = src[0];
        dst[1] = src[1];
        dst[2] = src[2];
        dst[3] = src[3];
    }
    __syncthreads();

    unsigned qf[4][4];
#pragma unroll
    for (int kb4 = 0; kb4 < 4; kb4++)
        ldsm_x4(qf[kb4][0], qf[kb4][1], qf[kb4][2], qf[kb4][3],
                smaddr(&Qs[(w * 16) * AT_STRIDE + aRowOff + kb4 * 16]));

    float o[8][4];
#pragma unroll
    for (int nt = 0; nt < 8; nt++)
#pragma unroll
        for (int r = 0; r < 4; r++) o[nt][r] = 0.f;
    float mA = -1e30f, mB = -1e30f, lA = 0.f, lB = 0.f;

    for (int kt = 0; kt < 16; kt++) {
        asm volatile("cp.async.wait_group 0;" ::: "memory");
        __syncthreads();
        if (kt + 1 < 16) issue_tile(kt + 1);
        const bf16* Ks = Kb[kt & 1];
        const bf16* Vs = Vb[kt & 1];

        // ---- QK^T ----
        float s[8][4];
#pragma unroll
        for (int nt = 0; nt < 8; nt++)
#pragma unroll
            for (int r = 0; r < 4; r++) s[nt][r] = 0.f;
#pragma unroll
        for (int kb4 = 0; kb4 < 4; kb4++) {
#pragma unroll
            for (int nt = 0; nt < 8; nt++) {
                unsigned b0, b1;
                ldsm_x2(b0, b1, smaddr(&Ks[(nt * 8) * AT_STRIDE + bRowOff + kb4 * 16]));
                mma_bf16(s[nt], qf[kb4][0], qf[kb4][1], qf[kb4][2], qf[kb4][3], b0, b1);
            }
        }

        // ---- online softmax (rows gid, gid+8) ----
        float tmA = -1e30f, tmB = -1e30f;
#pragma unroll
        for (int nt = 0; nt < 8; nt++) {
            tmA = fmaxf(tmA, fmaxf(s[nt][0], s[nt][1]));
            tmB = fmaxf(tmB, fmaxf(s[nt][2], s[nt][3]));
        }
        tmA = fmaxf(tmA, __shfl_xor_sync(0xffffffffu, tmA, 1));
        tmA = fmaxf(tmA, __shfl_xor_sync(0xffffffffu, tmA, 2));
        tmB = fmaxf(tmB, __shfl_xor_sync(0xffffffffu, tmB, 1));
        tmB = fmaxf(tmB, __shfl_xor_sync(0xffffffffu, tmB, 2));
        float nmA = fmaxf(mA, tmA), nmB = fmaxf(mB, tmB);
        float corrA = __expf(mA - nmA), corrB = __expf(mB - nmB);
        mA = nmA; mB = nmB;
        float sumA = 0.f, sumB = 0.f;
#pragma unroll
        for (int nt = 0; nt < 8; nt++) {
            s[nt][0] = __expf(s[nt][0] - nmA);
            s[nt][1] = __expf(s[nt][1] - nmA);
            s[nt][2] = __expf(s[nt][2] - nmB);
            s[nt][3] = __expf(s[nt][3] - nmB);
            sumA += s[nt][0] + s[nt][1];
            sumB += s[nt][2] + s[nt][3];
        }
        sumA += __shfl_xor_sync(0xffffffffu, sumA, 1);
        sumA += __shfl_xor_sync(0xffffffffu, sumA, 2);
        sumB += __shfl_xor_sync(0xffffffffu, sumB, 1);
        sumB += __shfl_xor_sync(0xffffffffu, sumB, 2);
        lA = lA * corrA + sumA;
        lB = lB * corrB + sumB;
#pragma unroll
        for (int nt = 0; nt < 8; nt++) {
            o[nt][0] *= corrA; o[nt][1] *= corrA;
            o[nt][2] *= corrB; o[nt][3] *= corrB;
        }
        // store P (bf16)
#pragma unroll
        for (int nt = 0; nt < 8; nt++) {
            int rq = w * 16 + gid;
            *(unsigned*)&Ps[rq * AT_STRIDE + nt * 8 + 2 * tig] = f2bf(s[nt][0], s[nt][1]);
            *(unsigned*)&Ps[(rq + 8) * AT_STRIDE + nt * 8 + 2 * tig] = f2bf(s[nt][2], s[nt][3]);
        }
        __syncwarp();

        // ---- PV ----
#pragma unroll
        for (int kc4 = 0; kc4 < 4; kc4++) {
            unsigned pf[4];
            ldsm_x4(pf[0], pf[1], pf[2], pf[3],
                    smaddr(&Ps[(w * 16) * AT_STRIDE + aRowOff + kc4 * 16]));
#pragma unroll
            for (int nt = 0; nt < 8; nt++) {
                unsigned b0, b1;
                ldsm_x2(b0, b1, smaddr(&Vs[(nt * 8) * AT_STRIDE + bRowOff + kc4 * 16]));
                mma_bf16(o[nt], pf[0], pf[1], pf[2], pf[3], b0, b1);
            }
        }
        __syncthreads();
    }

    // ---- epilogue ----
    float invA = 1.0f / lA, invB = 1.0f / lB;
    size_t rowA = (bS + q0 + w * 16 + gid) * 1024 + h * 64;
    size_t rowB = (bS + q0 + w * 16 + gid + 8) * 1024 + h * 64;
#pragma unroll
    for (int nt = 0; nt < 8; nt++) {
        int col = nt * 8 + 2 * tig;
        *(unsigned*)&out[rowA + col] = f2bf(o[nt][0] * invA, o[nt][1] * invA);
        *(unsigned*)&out[rowB + col] = f2bf(o[nt][2] * invB, o[nt][3] * invB);
    }
}

// ---------------- launch ----------------
extern "C" void kernel_launch(void* const* d_in, const int* in_sizes, int n_in,
                              void* d_out, int out_size) {
    const float* x       = (const float*)d_in[0];
    const float* c       = (const float*)d_in[1];
    const float* norm1_w = (const float*)d_in[2];
    const float* norm2_w = (const float*)d_in[3];
    const float* w_qkv   = (const float*)d_in[4];
    const float* w_out   = (const float*)d_in[5];
    const float* w1      = (const float*)d_in[6];
    const float* b1      = (const float*)d_in[7];
    const float* w2      = (const float*)d_in[8];
    const float* b2      = (const float*)d_in[9];
    const float* adaLN_w = (const float*)d_in[10];
    const float* adaLN_b = (const float*)d_in[11];
    const float* cosb    = (const float*)d_in[12];
    const float* sinb    = (const float*)d_in[13];
    float* out = (float*)d_out;

    float *mod, *x1;
    bf16 *xm, *qkv, *attn, *hbuf, *vt, *wqkv_t, *wout_t, *w1_t, *w2_t;
    cudaGetSymbolAddress((void**)&mod,  g_mod);
    cudaGetSymbolAddress((void**)&xm,   g_xm);
    cudaGetSymbolAddress((void**)&qkv,  g_qkv);
    cudaGetSymbolAddress((void**)&attn, g_attn);
    cudaGetSymbolAddress((void**)&x1,   g_x1);
    cudaGetSymbolAddress((void**)&hbuf, g_h);
    cudaGetSymbolAddress((void**)&vt,   g_vt);
    cudaGetSymbolAddress((void**)&wqkv_t, g_wqkv_t);
    cudaGetSymbolAddress((void**)&wout_t, g_wout_t);
    cudaGetSymbolAddress((void**)&w1_t,   g_w1_t);
    cudaGetSymbolAddress((void**)&w2_t,   g_w2_t);

    cudaFuncSetAttribute(attn_mma_kernel, cudaFuncAttributeMaxDynamicSharedMemorySize,
                         AT_SMEM_BYTES);
    cudaFuncSetAttribute(tgemm<1>, cudaFuncAttributeMaxDynamicSharedMemorySize, TG_BYTES);
    cudaFuncSetAttribute(tgemm<2>, cudaFuncAttributeMaxDynamicSharedMemorySize, TG_BYTES);
    cudaFuncSetAttribute(tgemm<3>, cudaFuncAttributeMaxDynamicSharedMemorySize, TG_BYTES);

    // 0) transpose + convert all weights to bf16 [N][K] (single launch)
    wtrans_all_kernel<<<12288, dim3(32, 8)>>>(w_qkv, w_out, w1, w2,
                                              wqkv_t, wout_t, w1_t, w2_t);

    // 1) adaLN modulation vector
    mod_kernel<<<(BB * MODW + 255) / 256, 256>>>(c, adaLN_w, adaLN_b, mod);

    // 2) LN1 + modulate
    ln_mod_kernel<<<BB * SS, 256>>>(x, norm1_w, mod, 0, 1, xm);

    // 3) QKV GEMM -> bf16 qkv
    tgemm<3><<<dim3(3072 / 128, 4096 / 128), 128, TG_BYTES>>>(
        xm, wqkv_t, nullptr, nullptr, nullptr, 0, qkv, BB * SS, 3 * DD, DD);

    // 4) RoPE in place (q scaled 1/8); V transpose -> vt
    rope_bf16_kernel<<<(BB * SS * 2 * HH * 32) / 256, 256>>>(qkv, cosb, sinb);
    vtrans_kernel<<<dim3(32, 32, 4), dim3(32, 8)>>>(qkv, vt);

    // 5) attention -> bf16 attn
    attn_mma_kernel<<<dim3(BB * HH, SS / 64), 128, AT_SMEM_BYTES>>>(qkv, vt, attn);

    // 6) out-proj + gated residual -> fp32 x1
    tgemm<2><<<dim3(1024 / 128, 4096 / 128), 128, TG_BYTES>>>(
        attn, wout_t, nullptr, x, mod, 2 * DD, x1, BB * SS, DD, DD);

    // 7) LN2 + modulate
    ln_mod_kernel<<<BB * SS, 256>>>(x1, norm2_w, mod, 3, 4, xm);

    // 8) MLP up + GELU -> bf16 h
    tgemm<1><<<dim3(MLPD / 128, 4096 / 128), 128, TG_BYTES>>>(
        xm, w1_t, b1, nullptr, nullptr, 0, hbuf, BB * SS, MLPD, DD);

    // 9) MLP down + gated residual -> fp32 out
    tgemm<2><<<dim3(1024 / 128, 4096 / 128), 128, TG_BYTES>>>(
        hbuf, w2_t, b2, x1, mod, 5 * DD, out, BB * SS, DD, MLPD);
}

// round 13
// speedup vs baseline: 1.0271x; 1.0271x over previous
#include <cuda_runtime.h>
#include <cuda_bf16.h>
#include <cstdint>
#include <math.h>

// Problem constants
#define BB 4
#define SS 1024
#define DD 1024
#define HH 16
#define HD 64
#define MLPD 4096
#define MODW 6144   // 6*D
#define LN_EPS 1e-5f

typedef __nv_bfloat16 bf16;
typedef __nv_bfloat162 bf162;

// ---------------- scratch (no allocs allowed) ----------------
__device__ float g_mod[BB * MODW];
__device__ bf16  g_xm[(size_t)BB * SS * DD];
__device__ bf16  g_qkv[(size_t)BB * SS * 3 * DD];        // bf16; q,k roped at GEMM epilogue
__device__ bf16  g_attn[(size_t)BB * SS * DD];
__device__ float g_x1[(size_t)BB * SS * DD];
__device__ bf16  g_h[(size_t)BB * SS * MLPD];
__device__ bf16  g_vt[(size_t)BB * HH * HD * SS];        // V^T [b][h][d][s]
// transposed bf16 weights [N][K]
__device__ bf16 g_wqkv_t[(size_t)3 * DD * DD];
__device__ bf16 g_wout_t[(size_t)DD * DD];
__device__ bf16 g_w1_t[(size_t)MLPD * DD];
__device__ bf16 g_w2_t[(size_t)DD * MLPD];

// ---------------- helpers ----------------
__device__ __forceinline__ unsigned smaddr(const void* p) {
    return (unsigned)__cvta_generic_to_shared(p);
}
__device__ __forceinline__ void ldsm_x4(unsigned& r0, unsigned& r1, unsigned& r2,
                                        unsigned& r3, unsigned a) {
    asm volatile("ldmatrix.sync.aligned.m8n8.x4.shared.b16 {%0,%1,%2,%3},[%4];"
                 : "=r"(r0), "=r"(r1), "=r"(r2), "=r"(r3) : "r"(a));
}
__device__ __forceinline__ void ldsm_x2(unsigned& r0, unsigned& r1, unsigned a) {
    asm volatile("ldmatrix.sync.aligned.m8n8.x2.shared.b16 {%0,%1},[%2];"
                 : "=r"(r0), "=r"(r1) : "r"(a));
}
__device__ __forceinline__ void mma_bf16(float c[4], unsigned a0, unsigned a1,
                                         unsigned a2, unsigned a3,
                                         unsigned b0, unsigned b1) {
    asm volatile("mma.sync.aligned.m16n8k16.row.col.f32.bf16.bf16.f32 "
                 "{%0,%1,%2,%3}, {%4,%5,%6,%7}, {%8,%9}, {%0,%1,%2,%3};"
                 : "+f"(c[0]), "+f"(c[1]), "+f"(c[2]), "+f"(c[3])
                 : "r"(a0), "r"(a1), "r"(a2), "r"(a3), "r"(b0), "r"(b1));
}
__device__ __forceinline__ void cp16(void* s, const void* g) {
    asm volatile("cp.async.cg.shared.global [%0], [%1], 16;"
                 :: "r"(smaddr(s)), "l"(g));
}
__device__ __forceinline__ unsigned f2bf(float x, float y) {
    bf162 t = __floats2bfloat162_rn(x, y);
    return *(unsigned*)&t;
}

// ---------------- merged weight transpose + bf16 convert + adaLN mod ----------
// blocks [0,12288): weight 32x32 transpose tiles; blocks [12288,12384): mod vector
__global__ void wtrans_all_kernel(const float* __restrict__ s0, const float* __restrict__ s1,
                                  const float* __restrict__ s2, const float* __restrict__ s3,
                                  bf16* __restrict__ d0, bf16* __restrict__ d1,
                                  bf16* __restrict__ d2, bf16* __restrict__ d3,
                                  const float* __restrict__ c, const float* __restrict__ aw,
                                  const float* __restrict__ ab, float* __restrict__ mod) {
    __shared__ float t[32][33];
    int tb = blockIdx.x;
    int tx = threadIdx.x, ty = threadIdx.y;
    if (tb >= 12288) {
        int n = (tb - 12288) * 256 + ty * 32 + tx;      // [0, 24576)
        int b = n / MODW;
        int col = n - b * MODW;
        float acc = ab[col];
        const float* cb = c + b * 128;
#pragma unroll 8
        for (int k = 0; k < 128; k++) acc = fmaf(cb[k], aw[(size_t)k * MODW + col], acc);
        mod[n] = acc;
        return;
    }
    const float* src; bf16* dst; int K, N;
    if (tb < 3072)      { src = s0; dst = d0; K = 1024; N = 3072; }
    else if (tb < 4096) { tb -= 3072; src = s1; dst = d1; K = 1024; N = 1024; }
    else if (tb < 8192) { tb -= 4096; src = s2; dst = d2; K = 1024; N = 4096; }
    else                { tb -= 8192; src = s3; dst = d3; K = 4096; N = 1024; }
    int ntn = N >> 5;
    int k0 = (tb / ntn) * 32, n0 = (tb % ntn) * 32;
#pragma unroll
    for (int j = ty; j < 32; j += 8)
        t[j][tx] = src[(size_t)(k0 + j) * N + n0 + tx];
    __syncthreads();
#pragma unroll
    for (int j = ty; j < 32; j += 8)
        dst[(size_t)(n0 + j) * K + k0 + tx] = __float2bfloat16_rn(t[tx][j]);
}

// ---------------- fused LayerNorm + modulate (vectorized, bf16 out) -----------
__global__ __launch_bounds__(256)
void ln_mod_kernel(const float* __restrict__ x, const float* __restrict__ w,
                   const float* __restrict__ mod, int shiftSeg, int scaleSeg,
                   bf16* __restrict__ out) {
    __shared__ float r1[8], r2[8];
    int row = blockIdx.x;
    int b = row >> 10;
    int tid = threadIdx.x, lane = tid & 31, wrp = tid >> 5;
    float4 v = ((const float4*)(x + (size_t)row * DD))[tid];
    float s = v.x + v.y + v.z + v.w;
    float ss = v.x * v.x + v.y * v.y + v.z * v.z + v.w * v.w;
#pragma unroll
    for (int o = 16; o > 0; o >>= 1) {
        s  += __shfl_xor_sync(0xffffffffu, s, o);
        ss += __shfl_xor_sync(0xffffffffu, ss, o);
    }
    if (lane == 0) { r1[wrp] = s; r2[wrp] = ss; }
    __syncthreads();
    if (wrp == 0) {
        float a = (lane < 8) ? r1[lane] : 0.f;
        float c2 = (lane < 8) ? r2[lane] : 0.f;
#pragma unroll
        for (int o = 4; o > 0; o >>= 1) {
            a  += __shfl_xor_sync(0xffffffffu, a, o);
            c2 += __shfl_xor_sync(0xffffffffu, c2, o);
        }
        if (lane == 0) { r1[0] = a; r2[0] = c2; }
    }
    __syncthreads();
    float mu = r1[0] * (1.0f / DD);
    float var = r2[0] * (1.0f / DD) - mu * mu;
    float rstd = rsqrtf(var + LN_EPS);
    float4 wv = ((const float4*)w)[tid];
    float4 sh = ((const float4*)(mod + (size_t)b * MODW + shiftSeg * DD))[tid];
    float4 sc = ((const float4*)(mod + (size_t)b * MODW + scaleSeg * DD))[tid];
    float y0 = fmaf((v.x - mu) * rstd * wv.x, 1.0f + sc.x, sh.x);
    float y1 = fmaf((v.y - mu) * rstd * wv.y, 1.0f + sc.y, sh.y);
    float y2 = fmaf((v.z - mu) * rstd * wv.z, 1.0f + sc.z, sh.z);
    float y3 = fmaf((v.w - mu) * rstd * wv.w, 1.0f + sc.w, sh.w);
    uint2 o2 = make_uint2(f2bf(y0, y1), f2bf(y2, y3));
    *(uint2*)(out + (size_t)row * DD + tid * 4) = o2;
}

__device__ __forceinline__ float gelu_tanh(float x) {
    float x3 = x * x * x;
    return 0.5f * x * (1.0f + tanhf(0.7978845608028654f * (x + 0.044715f * x3)));
}

// ---------------- bf16 tensor-core GEMM: 4 warps, warp tile 64x64 -------------
// CTA 128x128, K-stage 32, 128 threads (2x2 warps of 64x64), 4-stage cp.async.
// As[m][k], Bs[n][k], stride 40 halves.
// EPI 1: bf16 C = gelu(acc+bias)   EPI 2: fp32 C = resid + mod*(acc+bias?)
// EPI 3: bf16 C = acc              EPI 4: QKV rope epilogue (bf16)
#define TG_STRIDE 40
#define TG_HBUF (128 * TG_STRIDE)
#define TG_STAGE (2 * TG_HBUF)
#define TG_BYTES (4 * TG_STAGE * 2)              // 81920 B

template<int EPI>
__global__ __launch_bounds__(128, 2)
void tgemm(const bf16* __restrict__ A, const bf16* __restrict__ Bt,
           const float* __restrict__ bias, const float* __restrict__ resid,
           const float* __restrict__ mod, int modOff,
           const float* __restrict__ cosb, const float* __restrict__ sinb,
           void* __restrict__ Cv, int M, int N, int K) {
    extern __shared__ bf16 smh[];
    const int tid = threadIdx.x;
    const int lane = tid & 31, wid = tid >> 5;
    const int gid = lane >> 2, tig = lane & 3;
    const int bx = blockIdx.x, by = blockIdx.y;
    const int m0w = (wid & 1) * 64;
    const int n0w = (wid >> 1) * 64;

    const int aRowOff = (lane & 15) * TG_STRIDE + 8 * (lane >> 4);
    const int bRowOff = (lane & 7) * TG_STRIDE + 8 * ((lane >> 3) & 1);

    const bf16* Ag = A + (size_t)(by * 128) * K;
    const bf16* Bg = Bt + (size_t)(bx * 128) * K;

    float acc[4][8][4];
#pragma unroll
    for (int i = 0; i < 4; i++)
#pragma unroll
        for (int j = 0; j < 8; j++)
#pragma unroll
            for (int r = 0; r < 4; r++) acc[i][j][r] = 0.f;

    const int NS = K >> 5;

    auto issue = [&](int ks) {
        bf16* As = smh + (ks & 3) * TG_STAGE;
        bf16* Bs = As + TG_HBUF;
#pragma unroll
        for (int e = 0; e < 4; e++) {
            int idx = tid + e * 128;            // [0,512)
            int row = idx >> 2, q = idx & 3;
            cp16(&As[row * TG_STRIDE + q * 8], Ag + (size_t)row * K + ks * 32 + q * 8);
        }
#pragma unroll
        for (int e = 0; e < 4; e++) {
            int idx = tid + e * 128;
            int row = idx >> 2, q = idx & 3;
            cp16(&Bs[row * TG_STRIDE + q * 8], Bg + (size_t)row * K + ks * 32 + q * 8);
        }
        asm volatile("cp.async.commit_group;");
    };

    issue(0); issue(1); issue(2);

    for (int ks = 0; ks < NS; ks++) {
        if (ks + 2 < NS) asm volatile("cp.async.wait_group 2;" ::: "memory");
        else             asm volatile("cp.async.wait_group 0;" ::: "memory");
        __syncthreads();
        if (ks + 3 < NS) issue(ks + 3);
        const bf16* As = smh + (ks & 3) * TG_STAGE;
        const bf16* Bs = As + TG_HBUF;

        unsigned afA[4][4], bfA[8][2], afB[4][4], bfB[8][2];
#pragma unroll
        for (int mt = 0; mt < 4; mt++)
            ldsm_x4(afA[mt][0], afA[mt][1], afA[mt][2], afA[mt][3],
                    smaddr(&As[(m0w + mt * 16) * TG_STRIDE + aRowOff]));
#pragma unroll
        for (int nt = 0; nt < 8; nt++)
            ldsm_x2(bfA[nt][0], bfA[nt][1],
                    smaddr(&Bs[(n0w + nt * 8) * TG_STRIDE + bRowOff]));
#pragma unroll
        for (int mt = 0; mt < 4; mt++)
            ldsm_x4(afB[mt][0], afB[mt][1], afB[mt][2], afB[mt][3],
                    smaddr(&As[(m0w + mt * 16) * TG_STRIDE + aRowOff + 16]));
#pragma unroll
        for (int nt = 0; nt < 8; nt++)
            ldsm_x2(bfB[nt][0], bfB[nt][1],
                    smaddr(&Bs[(n0w + nt * 8) * TG_STRIDE + bRowOff + 16]));

#pragma unroll
        for (int mt = 0; mt < 4; mt++)
#pragma unroll
            for (int nt = 0; nt < 8; nt++)
                mma_bf16(acc[mt][nt], afA[mt][0], afA[mt][1], afA[mt][2], afA[mt][3],
                         bfA[nt][0], bfA[nt][1]);
#pragma unroll
        for (int mt = 0; mt < 4; mt++)
#pragma unroll
            for (int nt = 0; nt < 8; nt++)
                mma_bf16(acc[mt][nt], afB[mt][0], afB[mt][1], afB[mt][2], afB[mt][3],
                         bfB[nt][0], bfB[nt][1]);
    }

    // ---- epilogue ----
    if (EPI == 4) {
        // QKV with fused RoPE. Warp owns a 64-wide head-aligned column range.
        int colBase = bx * 128 + n0w;          // warp-uniform, 64-aligned
        int sel = colBase >> 10;               // 0=q, 1=k, 2=v
        bf16* C = (bf16*)Cv;
        if (sel == 2) {
#pragma unroll
            for (int mt = 0; mt < 4; mt++)
#pragma unroll
                for (int half = 0; half < 2; half++) {
                    int row = by * 128 + m0w + mt * 16 + gid + 8 * half;
                    size_t rowBase = (size_t)row * N;
#pragma unroll
                    for (int nt = 0; nt < 8; nt++) {
                        int col = colBase + nt * 8 + 2 * tig;
                        *(unsigned*)&C[rowBase + col] =
                            f2bf(acc[mt][nt][2 * half], acc[mt][nt][2 * half + 1]);
                    }
                }
        } else {
            float scale = sel ? 1.0f : 0.125f;
#pragma unroll
            for (int mt = 0; mt < 4; mt++)
#pragma unroll
                for (int half = 0; half < 2; half++) {
                    int row = by * 128 + m0w + mt * 16 + gid + 8 * half;
                    int s = row & (SS - 1);
                    size_t rowBase = (size_t)row * N;
#pragma unroll
                    for (int nt = 0; nt < 4; nt++) {
                        int e0 = nt * 8 + 2 * tig;          // 0..31
                        float c0 = cosb[s * 32 + e0], c1 = cosb[s * 32 + e0 + 1];
                        float sv0 = sinb[s * 32 + e0], sv1 = sinb[s * 32 + e0 + 1];
                        float t1a = acc[mt][nt][2 * half];
                        float t1b = acc[mt][nt][2 * half + 1];
                        float t2a = acc[mt][nt + 4][2 * half];
                        float t2b = acc[mt][nt + 4][2 * half + 1];
                        int col = colBase + e0;
                        *(unsigned*)&C[rowBase + col] =
                            f2bf((t1a * c0 - t2a * sv0) * scale,
                                 (t1b * c1 - t2b * sv1) * scale);
                        *(unsigned*)&C[rowBase + col + 32] =
                            f2bf((t2a * c0 + t1a * sv0) * scale,
                                 (t2b * c1 + t1b * sv1) * scale);
                    }
                }
        }
        return;
    }

#pragma unroll
    for (int mt = 0; mt < 4; mt++) {
#pragma unroll
        for (int half = 0; half < 2; half++) {
            int row = by * 128 + m0w + mt * 16 + gid + 8 * half;
            size_t rowBase = (size_t)row * N;
#pragma unroll
            for (int nt = 0; nt < 8; nt++) {
                int col = bx * 128 + n0w + nt * 8 + 2 * tig;
                float v0 = acc[mt][nt][2 * half];
                float v1 = acc[mt][nt][2 * half + 1];
                if (EPI == 1) {
                    v0 = gelu_tanh(v0 + bias[col]);
                    v1 = gelu_tanh(v1 + bias[col + 1]);
                    *(unsigned*)&((bf16*)Cv)[rowBase + col] = f2bf(v0, v1);
                } else if (EPI == 2) {
                    if (bias) { v0 += bias[col]; v1 += bias[col + 1]; }
                    size_t mb = (size_t)(row >> 10) * MODW + modOff + col;
                    float g0 = mod[mb], g1 = mod[mb + 1];
                    float2 rr = *(const float2*)&resid[rowBase + col];
                    *(float2*)&((float*)Cv)[rowBase + col] =
                        make_float2(fmaf(g0, v0, rr.x), fmaf(g1, v1, rr.y));
                } else {
                    *(unsigned*)&((bf16*)Cv)[rowBase + col] = f2bf(v0, v1);
                }
            }
        }
    }
}

// ---------------- V transpose: bf16 qkv v-part -> vt[b][h][d][s] --------------
__global__ void vtrans_kernel(const bf16* __restrict__ qkv, bf16* __restrict__ vt) {
    __shared__ bf16 t[32][34];
    int b = blockIdx.z;
    int s0 = blockIdx.x * 32, hd0 = blockIdx.y * 32;
    int tx = threadIdx.x, ty = threadIdx.y;
#pragma unroll
    for (int j = ty; j < 32; j += 8)
        t[j][tx] = qkv[(size_t)(b * 1024 + s0 + j) * 3072 + 2048 + hd0 + tx];
    __syncthreads();
#pragma unroll
    for (int j = ty; j < 32; j += 8)
        vt[(size_t)(b * 1024 + hd0 + j) * 1024 + s0 + tx] = t[tx][j];
}

// ---------------- attention: flash, bf16 mma, ldmatrix, cp.async K/V ----------
#define AT_STRIDE 72
#define AT_HBUF (64 * AT_STRIDE)
#define AT_SMEM_BYTES (6 * AT_HBUF * 2)          // 55296 B

__global__ __launch_bounds__(128, 3)
void attn_mma_kernel(const bf16* __restrict__ qkv, const bf16* __restrict__ vt,
                     bf16* __restrict__ out) {
    extern __shared__ bf16 smh[];
    bf16* Qs = smh;
    bf16* Ps = Qs + AT_HBUF;
    bf16* Kb[2] = { Ps + AT_HBUF, Ps + 3 * AT_HBUF };
    bf16* Vb[2] = { Ps + 2 * AT_HBUF, Ps + 4 * AT_HBUF };
    int bh = blockIdx.x;
    int b = bh >> 4, h = bh & 15;
    size_t bS = (size_t)b * SS;
    int q0 = blockIdx.y * 64;
    int tid = threadIdx.x, w = tid >> 5, lane = tid & 31;
    int gid = lane >> 2, tig = lane & 3;
    const int aRowOff = (lane & 15) * AT_STRIDE + 8 * (lane >> 4);
    const int bRowOff = (lane & 7) * AT_STRIDE + 8 * ((lane >> 3) & 1);

    const bf16* vbase = vt + ((size_t)(b * 1024 + h * 64)) * 1024;

    auto issue_tile = [&](int kt) {
        int kb0 = kt * 64;
        bf16* Ks = Kb[kt & 1];
        bf16* Vs = Vb[kt & 1];
#pragma unroll
        for (int e = 0; e < 4; e++) {
            int idx = tid + e * 128;            // [0,512)
            int r = idx >> 3, q = idx & 7;
            cp16(&Ks[r * AT_STRIDE + q * 8],
                 qkv + (bS + kb0 + r) * 3072 + 1024 + h * 64 + q * 8);
            cp16(&Vs[r * AT_STRIDE + q * 8],
                 vbase + (size_t)r * 1024 + kb0 + q * 8);
        }
        asm volatile("cp.async.commit_group;");
    };

    issue_tile(0);

    // stage Q (already roped + scaled)
    {
        int q = tid >> 1, d0 = (tid & 1) * 32;
        const uint4* src = (const uint4*)(qkv + (bS + q0 + q) * 3072 + h * 64 + d0);
        uint4* dst = (uint4*)&Qs[q * AT_STRIDE + d0];
        dst[0] = src[0];
        dst[1] = src[1];
        dst[2] = src[2];
        dst[3] = src[3];
    }
    __syncthreads();

    unsigned qf[4][4];
#pragma unroll
    for (int kb4 = 0; kb4 < 4; kb4++)
        ldsm_x4(qf[kb4][0], qf[kb4][1], qf[kb4][2], qf[kb4][3],
                smaddr(&Qs[(w * 16) * AT_STRIDE + aRowOff + kb4 * 16]));

    float o[8][4];
#pragma unroll
    for (int nt = 0; nt < 8; nt++)
#pragma unroll
        for (int r = 0; r < 4; r++) o[nt][r] = 0.f;
    float mA = -1e30f, mB = -1e30f, lA = 0.f, lB = 0.f;

    for (int kt = 0; kt < 16; kt++) {
        asm volatile("cp.async.wait_group 0;" ::: "memory");
        __syncthreads();
        if (kt + 1 < 16) issue_tile(kt + 1);
        const bf16* Ks = Kb[kt & 1];
        const bf16* Vs = Vb[kt & 1];

        // ---- QK^T ----
        float s[8][4];
#pragma unroll
        for (int nt = 0; nt < 8; nt++)
#pragma unroll
            for (int r = 0; r < 4; r++) s[nt][r] = 0.f;
#pragma unroll
        for (int kb4 = 0; kb4 < 4; kb4++) {
#pragma unroll
            for (int nt = 0; nt < 8; nt++) {
                unsigned b0, b1;
                ldsm_x2(b0, b1, smaddr(&Ks[(nt * 8) * AT_STRIDE + bRowOff + kb4 * 16]));
                mma_bf16(s[nt], qf[kb4][0], qf[kb4][1], qf[kb4][2], qf[kb4][3], b0, b1);
            }
        }

        // ---- online softmax (rows gid, gid+8) ----
        float tmA = -1e30f, tmB = -1e30f;
#pragma unroll
        for (int nt = 0; nt < 8; nt++) {
            tmA = fmaxf(tmA, fmaxf(s[nt][0], s[nt][1]));
            tmB = fmaxf(tmB, fmaxf(s[nt][2], s[nt][3]));
        }
        tmA = fmaxf(tmA, __shfl_xor_sync(0xffffffffu, tmA, 1));
        tmA = fmaxf(tmA, __shfl_xor_sync(0xffffffffu, tmA, 2));
        tmB = fmaxf(tmB, __shfl_xor_sync(0xffffffffu, tmB, 1));
        tmB = fmaxf(tmB, __shfl_xor_sync(0xffffffffu, tmB, 2));
        float nmA = fmaxf(mA, tmA), nmB = fmaxf(mB, tmB);
        float corrA = __expf(mA - nmA), corrB = __expf(mB - nmB);
        mA = nmA; mB = nmB;
        float sumA = 0.f, sumB = 0.f;
#pragma unroll
        for (int nt = 0; nt < 8; nt++) {
            s[nt][0] = __expf(s[nt][0] - nmA);
            s[nt][1] = __expf(s[nt][1] - nmA);
            s[nt][2] = __expf(s[nt][2] - nmB);
            s[nt][3] = __expf(s[nt][3] - nmB);
            sumA += s[nt][0] + s[nt][1];
            sumB += s[nt][2] + s[nt][3];
        }
        sumA += __shfl_xor_sync(0xffffffffu, sumA, 1);
        sumA += __shfl_xor_sync(0xffffffffu, sumA, 2);
        sumB += __shfl_xor_sync(0xffffffffu, sumB, 1);
        sumB += __shfl_xor_sync(0xffffffffu, sumB, 2);
        lA = lA * corrA + sumA;
        lB = lB * corrB + sumB;
#pragma unroll
        for (int nt = 0; nt < 8; nt++) {
            o[nt][0] *= corrA; o[nt][1] *= corrA;
            o[nt][2] *= corrB; o[nt][3] *= corrB;
        }
        // store P (bf16)
#pragma unroll
        for (int nt = 0; nt < 8; nt++) {
            int rq = w * 16 + gid;
            *(unsigned*)&Ps[rq * AT_STRIDE + nt * 8 + 2 * tig] = f2bf(s[nt][0], s[nt][1]);
            *(unsigned*)&Ps[(rq + 8) * AT_STRIDE + nt * 8 + 2 * tig] = f2bf(s[nt][2], s[nt][3]);
        }
        __syncwarp();

        // ---- PV ----
#pragma unroll
        for (int kc4 = 0; kc4 < 4; kc4++) {
            unsigned pf[4];
            ldsm_x4(pf[0], pf[1], pf[2], pf[3],
                    smaddr(&Ps[(w * 16) * AT_STRIDE + aRowOff + kc4 * 16]));
#pragma unroll
            for (int nt = 0; nt < 8; nt++) {
                unsigned b0, b1;
                ldsm_x2(b0, b1, smaddr(&Vs[(nt * 8) * AT_STRIDE + bRowOff + kc4 * 16]));
                mma_bf16(o[nt], pf[0], pf[1], pf[2], pf[3], b0, b1);
            }
        }
        // NOTE: no trailing __syncthreads needed — the buffer written by
        // issue_tile(kt+1) was last read in iteration kt-1, which every thread
        // finished before this iteration's top-of-loop barrier.
    }

    // ---- epilogue ----
    float invA = 1.0f / lA, invB = 1.0f / lB;
    size_t rowA = (bS + q0 + w * 16 + gid) * 1024 + h * 64;
    size_t rowB = (bS + q0 + w * 16 + gid + 8) * 1024 + h * 64;
#pragma unroll
    for (int nt = 0; nt < 8; nt++) {
        int col = nt * 8 + 2 * tig;
        *(unsigned*)&out[rowA + col] = f2bf(o[nt][0] * invA, o[nt][1] * invA);
        *(unsigned*)&out[rowB + col] = f2bf(o[nt][2] * invB, o[nt][3] * invB);
    }
}

// ---------------- launch ----------------
extern "C" void kernel_launch(void* const* d_in, const int* in_sizes, int n_in,
                              void* d_out, int out_size) {
    const float* x       = (const float*)d_in[0];
    const float* c       = (const float*)d_in[1];
    const float* norm1_w = (const float*)d_in[2];
    const float* norm2_w = (const float*)d_in[3];
    const float* w_qkv   = (const float*)d_in[4];
    const float* w_out   = (const float*)d_in[5];
    const float* w1      = (const float*)d_in[6];
    const float* b1      = (const float*)d_in[7];
    const float* w2      = (const float*)d_in[8];
    const float* b2      = (const float*)d_in[9];
    const float* adaLN_w = (const float*)d_in[10];
    const float* adaLN_b = (const float*)d_in[11];
    const float* cosb    = (const float*)d_in[12];
    const float* sinb    = (const float*)d_in[13];
    float* out = (float*)d_out;

    float *mod, *x1;
    bf16 *xm, *qkv, *attn, *hbuf, *vt, *wqkv_t, *wout_t, *w1_t, *w2_t;
    cudaGetSymbolAddress((void**)&mod,  g_mod);
    cudaGetSymbolAddress((void**)&xm,   g_xm);
    cudaGetSymbolAddress((void**)&qkv,  g_qkv);
    cudaGetSymbolAddress((void**)&attn, g_attn);
    cudaGetSymbolAddress((void**)&x1,   g_x1);
    cudaGetSymbolAddress((void**)&hbuf, g_h);
    cudaGetSymbolAddress((void**)&vt,   g_vt);
    cudaGetSymbolAddress((void**)&wqkv_t, g_wqkv_t);
    cudaGetSymbolAddress((void**)&wout_t, g_wout_t);
    cudaGetSymbolAddress((void**)&w1_t,   g_w1_t);
    cudaGetSymbolAddress((void**)&w2_t,   g_w2_t);

    cudaFuncSetAttribute(attn_mma_kernel, cudaFuncAttributeMaxDynamicSharedMemorySize,
                         AT_SMEM_BYTES);
    cudaFuncSetAttribute(tgemm<1>, cudaFuncAttributeMaxDynamicSharedMemorySize, TG_BYTES);
    cudaFuncSetAttribute(tgemm<2>, cudaFuncAttributeMaxDynamicSharedMemorySize, TG_BYTES);
    cudaFuncSetAttribute(tgemm<4>, cudaFuncAttributeMaxDynamicSharedMemorySize, TG_BYTES);

    // 0) weights -> bf16 [N][K] transpose + adaLN mod vector (single launch)
    wtrans_all_kernel<<<12384, dim3(32, 8)>>>(w_qkv, w_out, w1, w2,
                                              wqkv_t, wout_t, w1_t, w2_t,
                                              c, adaLN_w, adaLN_b, mod);

    // 1) LN1 + modulate
    ln_mod_kernel<<<BB * SS, 256>>>(x, norm1_w, mod, 0, 1, xm);

    // 2) QKV GEMM with fused RoPE (q scaled 1/8) -> bf16 qkv
    tgemm<4><<<dim3(3072 / 128, 4096 / 128), 128, TG_BYTES>>>(
        xm, wqkv_t, nullptr, nullptr, nullptr, 0, cosb, sinb, qkv, BB * SS, 3 * DD, DD);

    // 3) V transpose -> vt
    vtrans_kernel<<<dim3(32, 32, 4), dim3(32, 8)>>>(qkv, vt);

    // 4) attention -> bf16 attn
    attn_mma_kernel<<<dim3(BB * HH, SS / 64), 128, AT_SMEM_BYTES>>>(qkv, vt, attn);

    // 5) out-proj + gated residual -> fp32 x1
    tgemm<2><<<dim3(1024 / 128, 4096 / 128), 128, TG_BYTES>>>(
        attn, wout_t, nullptr, x, mod, 2 * DD, nullptr, nullptr, x1, BB * SS, DD, DD);

    // 6) LN2 + modulate
    ln_mod_kernel<<<BB * SS, 256>>>(x1, norm2_w, mod, 3, 4, xm);

    // 7) MLP up + GELU -> bf16 h
    tgemm<1><<<dim3(MLPD / 128, 4096 / 128), 128, TG_BYTES>>>(
        xm, w1_t, b1, nullptr, nullptr, 0, nullptr, nullptr, hbuf, BB * SS, MLPD, DD);

    // 8) MLP down + gated residual -> fp32 out
    tgemm<2><<<dim3(1024 / 128, 4096 / 128), 128, TG_BYTES>>>(
        hbuf, w2_t, b2, x1, mod, 5 * DD, nullptr, nullptr, out, BB * SS, DD, MLPD);
}

// round 15
// speedup vs baseline: 1.1232x; 1.0936x over previous
#include <cuda_runtime.h>
#include <cuda_bf16.h>
#include <cstdint>
#include <math.h>

// Problem constants
#define BB 4
#define SS 1024
#define DD 1024
#define HH 16
#define HD 64
#define MLPD 4096
#define MODW 6144   // 6*D
#define LN_EPS 1e-5f

typedef __nv_bfloat16 bf16;
typedef __nv_bfloat162 bf162;

// ---------------- scratch (no allocs allowed) ----------------
__device__ float g_mod[BB * MODW];
__device__ bf16  g_xm[(size_t)BB * SS * DD];
__device__ bf16  g_qkv[(size_t)BB * SS * 3 * DD];        // bf16; q,k roped at GEMM epilogue
__device__ bf16  g_attn[(size_t)BB * SS * DD];
__device__ float g_x1[(size_t)BB * SS * DD];
__device__ bf16  g_h[(size_t)BB * SS * MLPD];
__device__ bf16  g_vt[(size_t)BB * HH * HD * SS];        // V^T [b][h][d][s]
// transposed bf16 weights [N][K]
__device__ bf16 g_wqkv_t[(size_t)3 * DD * DD];
__device__ bf16 g_wout_t[(size_t)DD * DD];
__device__ bf16 g_w1_t[(size_t)MLPD * DD];
__device__ bf16 g_w2_t[(size_t)DD * MLPD];

// ---------------- helpers ----------------
__device__ __forceinline__ unsigned smaddr(const void* p) {
    return (unsigned)__cvta_generic_to_shared(p);
}
__device__ __forceinline__ void ldsm_x4(unsigned& r0, unsigned& r1, unsigned& r2,
                                        unsigned& r3, unsigned a) {
    asm volatile("ldmatrix.sync.aligned.m8n8.x4.shared.b16 {%0,%1,%2,%3},[%4];"
                 : "=r"(r0), "=r"(r1), "=r"(r2), "=r"(r3) : "r"(a));
}
__device__ __forceinline__ void ldsm_x2(unsigned& r0, unsigned& r1, unsigned a) {
    asm volatile("ldmatrix.sync.aligned.m8n8.x2.shared.b16 {%0,%1},[%2];"
                 : "=r"(r0), "=r"(r1) : "r"(a));
}
__device__ __forceinline__ void mma_bf16(float c[4], unsigned a0, unsigned a1,
                                         unsigned a2, unsigned a3,
                                         unsigned b0, unsigned b1) {
    asm volatile("mma.sync.aligned.m16n8k16.row.col.f32.bf16.bf16.f32 "
                 "{%0,%1,%2,%3}, {%4,%5,%6,%7}, {%8,%9}, {%0,%1,%2,%3};"
                 : "+f"(c[0]), "+f"(c[1]), "+f"(c[2]), "+f"(c[3])
                 : "r"(a0), "r"(a1), "r"(a2), "r"(a3), "r"(b0), "r"(b1));
}
__device__ __forceinline__ void cp16(void* s, const void* g) {
    asm volatile("cp.async.cg.shared.global [%0], [%1], 16;"
                 :: "r"(smaddr(s)), "l"(g));
}
__device__ __forceinline__ unsigned f2bf(float x, float y) {
    bf162 t = __floats2bfloat162_rn(x, y);
    return *(unsigned*)&t;
}

// ---------------- merged weight transpose (64x64 uint4) + adaLN mod -----------
// 64x64 tiles: wqkv 768, wout 256, w1 1024, w2 1024 -> [0,3072); mod [3072,3168)
// SMEM tile stride 68 floats = 272 B: rows 16B-aligned for float4 stores.
__global__ __launch_bounds__(256)
void wtrans_all_kernel(const float* __restrict__ s0, const float* __restrict__ s1,
                       const float* __restrict__ s2, const float* __restrict__ s3,
                       bf16* __restrict__ d0, bf16* __restrict__ d1,
                       bf16* __restrict__ d2, bf16* __restrict__ d3,
                       const float* __restrict__ c, const float* __restrict__ aw,
                       const float* __restrict__ ab, float* __restrict__ mod) {
    __shared__ float t[64][68];
    int tb = blockIdx.x;
    int tid = threadIdx.x;
    if (tb >= 3072) {
        int n = (tb - 3072) * 256 + tid;                // [0, 24576)
        int b = n / MODW;
        int col = n - b * MODW;
        float acc = ab[col];
        const float* cb = c + b * 128;
#pragma unroll 8
        for (int k = 0; k < 128; k++) acc = fmaf(cb[k], aw[(size_t)k * MODW + col], acc);
        mod[n] = acc;
        return;
    }
    const float* src; bf16* dst; int K, N;
    if (tb < 768)       { src = s0; dst = d0; K = 1024; N = 3072; }
    else if (tb < 1024) { tb -= 768;  src = s1; dst = d1; K = 1024; N = 1024; }
    else if (tb < 2048) { tb -= 1024; src = s2; dst = d2; K = 1024; N = 4096; }
    else                { tb -= 2048; src = s3; dst = d3; K = 4096; N = 1024; }
    int ntn = N >> 6;
    int k0 = (tb / ntn) * 64, n0 = (tb % ntn) * 64;
#pragma unroll
    for (int e = 0; e < 4; e++) {
        int idx = tid + e * 256;                        // [0,1024)
        int row = idx >> 4, q = idx & 15;
        *(float4*)&t[row][q * 4] =
            *(const float4*)(src + (size_t)(k0 + row) * N + n0 + q * 4);
    }
    __syncthreads();
    // lanes: j = idx & 63 (column), q = idx >> 6 (k-group) -> conflict-free column reads
#pragma unroll
    for (int e = 0; e < 2; e++) {
        int idx = tid + e * 256;                        // [0,512)
        int j = idx & 63, q = idx >> 6;                 // q in [0,8) over both iters
        bf16 v[8];
#pragma unroll
        for (int i = 0; i < 8; i++) v[i] = __float2bfloat16_rn(t[q * 8 + i][j]);
        *(uint4*)(dst + (size_t)(n0 + j) * K + k0 + q * 8) = *(uint4*)v;
    }
}

// ---------------- fused LayerNorm + modulate (vectorized, bf16 out) -----------
__global__ __launch_bounds__(256)
void ln_mod_kernel(const float* __restrict__ x, const float* __restrict__ w,
                   const float* __restrict__ mod, int shiftSeg, int scaleSeg,
                   bf16* __restrict__ out) {
    __shared__ float r1[8], r2[8];
    int row = blockIdx.x;
    int b = row >> 10;
    int tid = threadIdx.x, lane = tid & 31, wrp = tid >> 5;
    float4 v = ((const float4*)(x + (size_t)row * DD))[tid];
    float s = v.x + v.y + v.z + v.w;
    float ss = v.x * v.x + v.y * v.y + v.z * v.z + v.w * v.w;
#pragma unroll
    for (int o = 16; o > 0; o >>= 1) {
        s  += __shfl_xor_sync(0xffffffffu, s, o);
        ss += __shfl_xor_sync(0xffffffffu, ss, o);
    }
    if (lane == 0) { r1[wrp] = s; r2[wrp] = ss; }
    __syncthreads();
    if (wrp == 0) {
        float a = (lane < 8) ? r1[lane] : 0.f;
        float c2 = (lane < 8) ? r2[lane] : 0.f;
#pragma unroll
        for (int o = 4; o > 0; o >>= 1) {
            a  += __shfl_xor_sync(0xffffffffu, a, o);
            c2 += __shfl_xor_sync(0xffffffffu, c2, o);
        }
        if (lane == 0) { r1[0] = a; r2[0] = c2; }
    }
    __syncthreads();
    float mu = r1[0] * (1.0f / DD);
    float var = r2[0] * (1.0f / DD) - mu * mu;
    float rstd = rsqrtf(var + LN_EPS);
    float4 wv = ((const float4*)w)[tid];
    float4 sh = ((const float4*)(mod + (size_t)b * MODW + shiftSeg * DD))[tid];
    float4 sc = ((const float4*)(mod + (size_t)b * MODW + scaleSeg * DD))[tid];
    float y0 = fmaf((v.x - mu) * rstd * wv.x, 1.0f + sc.x, sh.x);
    float y1 = fmaf((v.y - mu) * rstd * wv.y, 1.0f + sc.y, sh.y);
    float y2 = fmaf((v.z - mu) * rstd * wv.z, 1.0f + sc.z, sh.z);
    float y3 = fmaf((v.w - mu) * rstd * wv.w, 1.0f + sc.w, sh.w);
    uint2 o2 = make_uint2(f2bf(y0, y1), f2bf(y2, y3));
    *(uint2*)(out + (size_t)row * DD + tid * 4) = o2;
}

__device__ __forceinline__ float gelu_tanh(float x) {
    float x3 = x * x * x;
    return 0.5f * x * (1.0f + tanhf(0.7978845608028654f * (x + 0.044715f * x3)));
}

// ---------------- bf16 tensor-core GEMM: persistent tiles ---------------------
// CTA 128x128, K-stage 32, 128 threads (2x2 warps of 64x64), 4-stage cp.async.
// Grid-stride loop over tiles removes wave quantization.
#define TG_STRIDE 40
#define TG_HBUF (128 * TG_STRIDE)
#define TG_STAGE (2 * TG_HBUF)
#define TG_BYTES (4 * TG_STAGE * 2)              // 81920 B

template<int EPI>
__global__ __launch_bounds__(128, 2)
void tgemm(const bf16* __restrict__ A, const bf16* __restrict__ Bt,
           const float* __restrict__ bias, const float* __restrict__ resid,
           const float* __restrict__ mod, int modOff,
           const float* __restrict__ cosb, const float* __restrict__ sinb,
           void* __restrict__ Cv, int M, int N, int K) {
    extern __shared__ bf16 smh[];
    const int tid = threadIdx.x;
    const int lane = tid & 31, wid = tid >> 5;
    const int gid = lane >> 2, tig = lane & 3;
    const int m0w = (wid & 1) * 64;
    const int n0w = (wid >> 1) * 64;
    const int aRowOff = (lane & 15) * TG_STRIDE + 8 * (lane >> 4);
    const int bRowOff = (lane & 7) * TG_STRIDE + 8 * ((lane >> 3) & 1);
    const int NS = K >> 5;
    const int ntx = N >> 7;
    const int totalTiles = (M >> 7) * ntx;

    for (int tile = blockIdx.x; tile < totalTiles; tile += gridDim.x) {
        const int bx = tile % ntx, by = tile / ntx;
        const bf16* Ag = A + (size_t)(by * 128) * K;
        const bf16* Bg = Bt + (size_t)(bx * 128) * K;

        float acc[4][8][4];
#pragma unroll
        for (int i = 0; i < 4; i++)
#pragma unroll
            for (int j = 0; j < 8; j++)
#pragma unroll
                for (int r = 0; r < 4; r++) acc[i][j][r] = 0.f;

        auto issue = [&](int ks) {
            bf16* As = smh + (ks & 3) * TG_STAGE;
            bf16* Bs = As + TG_HBUF;
#pragma unroll
            for (int e = 0; e < 4; e++) {
                int idx = tid + e * 128;
                int row = idx >> 2, q = idx & 3;
                cp16(&As[row * TG_STRIDE + q * 8], Ag + (size_t)row * K + ks * 32 + q * 8);
            }
#pragma unroll
            for (int e = 0; e < 4; e++) {
                int idx = tid + e * 128;
                int row = idx >> 2, q = idx & 3;
                cp16(&Bs[row * TG_STRIDE + q * 8], Bg + (size_t)row * K + ks * 32 + q * 8);
            }
            asm volatile("cp.async.commit_group;");
        };

        issue(0); issue(1); issue(2);

        for (int ks = 0; ks < NS; ks++) {
            if (ks + 2 < NS) asm volatile("cp.async.wait_group 2;" ::: "memory");
            else             asm volatile("cp.async.wait_group 0;" ::: "memory");
            __syncthreads();
            if (ks + 3 < NS) issue(ks + 3);
            const bf16* As = smh + (ks & 3) * TG_STAGE;
            const bf16* Bs = As + TG_HBUF;

            unsigned afA[4][4], bfA[8][2], afB[4][4], bfB[8][2];
#pragma unroll
            for (int mt = 0; mt < 4; mt++)
                ldsm_x4(afA[mt][0], afA[mt][1], afA[mt][2], afA[mt][3],
                        smaddr(&As[(m0w + mt * 16) * TG_STRIDE + aRowOff]));
#pragma unroll
            for (int nt = 0; nt < 8; nt++)
                ldsm_x2(bfA[nt][0], bfA[nt][1],
                        smaddr(&Bs[(n0w + nt * 8) * TG_STRIDE + bRowOff]));
#pragma unroll
            for (int mt = 0; mt < 4; mt++)
                ldsm_x4(afB[mt][0], afB[mt][1], afB[mt][2], afB[mt][3],
                        smaddr(&As[(m0w + mt * 16) * TG_STRIDE + aRowOff + 16]));
#pragma unroll
            for (int nt = 0; nt < 8; nt++)
                ldsm_x2(bfB[nt][0], bfB[nt][1],
                        smaddr(&Bs[(n0w + nt * 8) * TG_STRIDE + bRowOff + 16]));

#pragma unroll
            for (int mt = 0; mt < 4; mt++)
#pragma unroll
                for (int nt = 0; nt < 8; nt++)
                    mma_bf16(acc[mt][nt], afA[mt][0], afA[mt][1], afA[mt][2], afA[mt][3],
                             bfA[nt][0], bfA[nt][1]);
#pragma unroll
            for (int mt = 0; mt < 4; mt++)
#pragma unroll
                for (int nt = 0; nt < 8; nt++)
                    mma_bf16(acc[mt][nt], afB[mt][0], afB[mt][1], afB[mt][2], afB[mt][3],
                             bfB[nt][0], bfB[nt][1]);
        }
        __syncthreads();   // all smem reads done before next tile's prologue

        // ---- epilogue ----
        if (EPI == 4) {
            int colBase = bx * 128 + n0w;          // warp-uniform, 64-aligned
            int sel = colBase >> 10;               // 0=q, 1=k, 2=v
            bf16* C = (bf16*)Cv;
            if (sel == 2) {
#pragma unroll
                for (int mt = 0; mt < 4; mt++)
#pragma unroll
                    for (int half = 0; half < 2; half++) {
                        int row = by * 128 + m0w + mt * 16 + gid + 8 * half;
                        size_t rowBase = (size_t)row * N;
#pragma unroll
                        for (int nt = 0; nt < 8; nt++) {
                            int col = colBase + nt * 8 + 2 * tig;
                            *(unsigned*)&C[rowBase + col] =
                                f2bf(acc[mt][nt][2 * half], acc[mt][nt][2 * half + 1]);
                        }
                    }
            } else {
                float scale = sel ? 1.0f : 0.125f;
#pragma unroll
                for (int mt = 0; mt < 4; mt++)
#pragma unroll
                    for (int half = 0; half < 2; half++) {
                        int row = by * 128 + m0w + mt * 16 + gid + 8 * half;
                        int s = row & (SS - 1);
                        size_t rowBase = (size_t)row * N;
#pragma unroll
                        for (int nt = 0; nt < 4; nt++) {
                            int e0 = nt * 8 + 2 * tig;
                            float c0 = cosb[s * 32 + e0], c1 = cosb[s * 32 + e0 + 1];
                            float sv0 = sinb[s * 32 + e0], sv1 = sinb[s * 32 + e0 + 1];
                            float t1a = acc[mt][nt][2 * half];
                            float t1b = acc[mt][nt][2 * half + 1];
                            float t2a = acc[mt][nt + 4][2 * half];
                            float t2b = acc[mt][nt + 4][2 * half + 1];
                            int col = colBase + e0;
                            *(unsigned*)&C[rowBase + col] =
                                f2bf((t1a * c0 - t2a * sv0) * scale,
                                     (t1b * c1 - t2b * sv1) * scale);
                            *(unsigned*)&C[rowBase + col + 32] =
                                f2bf((t2a * c0 + t1a * sv0) * scale,
                                     (t2b * c1 + t1b * sv1) * scale);
                        }
                    }
            }
        } else {
#pragma unroll
            for (int mt = 0; mt < 4; mt++) {
#pragma unroll
                for (int half = 0; half < 2; half++) {
                    int row = by * 128 + m0w + mt * 16 + gid + 8 * half;
                    size_t rowBase = (size_t)row * N;
#pragma unroll
                    for (int nt = 0; nt < 8; nt++) {
                        int col = bx * 128 + n0w + nt * 8 + 2 * tig;
                        float v0 = acc[mt][nt][2 * half];
                        float v1 = acc[mt][nt][2 * half + 1];
                        if (EPI == 1) {
                            v0 = gelu_tanh(v0 + bias[col]);
                            v1 = gelu_tanh(v1 + bias[col + 1]);
                            *(unsigned*)&((bf16*)Cv)[rowBase + col] = f2bf(v0, v1);
                        } else if (EPI == 2) {
                            if (bias) { v0 += bias[col]; v1 += bias[col + 1]; }
                            size_t mb = (size_t)(row >> 10) * MODW + modOff + col;
                            float g0 = mod[mb], g1 = mod[mb + 1];
                            float2 rr = *(const float2*)&resid[rowBase + col];
                            *(float2*)&((float*)Cv)[rowBase + col] =
                                make_float2(fmaf(g0, v0, rr.x), fmaf(g1, v1, rr.y));
                        } else {
                            *(unsigned*)&((bf16*)Cv)[rowBase + col] = f2bf(v0, v1);
                        }
                    }
                }
            }
        }
    }
}

// ---------------- V transpose: 64x64 uint4 tiles ------------------------------
__global__ __launch_bounds__(256)
void vtrans_kernel(const bf16* __restrict__ qkv, bf16* __restrict__ vt) {
    __shared__ bf16 t[64][72];
    int b = blockIdx.z;
    int s0 = blockIdx.x * 64, hd0 = blockIdx.y * 64;
    int tid = threadIdx.x;
#pragma unroll
    for (int e = 0; e < 2; e++) {
        int idx = tid + e * 256;                        // [0,512)
        int row = idx >> 3, q = idx & 7;
        *(uint4*)&t[row][q * 8] =
            *(const uint4*)(qkv + (size_t)(b * 1024 + s0 + row) * 3072 + 2048 + hd0 + q * 8);
    }
    __syncthreads();
#pragma unroll
    for (int e = 0; e < 2; e++) {
        int idx = tid + e * 256;
        int d = idx & 63, q = idx >> 6;                 // conflict-friendly mapping
        bf16 v[8];
#pragma unroll
        for (int i = 0; i < 8; i++) v[i] = t[q * 8 + i][d];
        *(uint4*)(vt + (size_t)(b * 1024 + hd0 + d) * 1024 + s0 + q * 8) = *(uint4*)v;
    }
}

// ---------------- attention: flash, bf16 mma, ldmatrix, cp.async K/V ----------
#define AT_STRIDE 72
#define AT_HBUF (64 * AT_STRIDE)
#define AT_SMEM_BYTES (6 * AT_HBUF * 2)          // 55296 B

__global__ __launch_bounds__(128, 3)
void attn_mma_kernel(const bf16* __restrict__ qkv, const bf16* __restrict__ vt,
                     bf16* __restrict__ out) {
    extern __shared__ bf16 smh[];
    bf16* Qs = smh;
    bf16* Ps = Qs + AT_HBUF;
    bf16* Kb[2] = { Ps + AT_HBUF, Ps + 3 * AT_HBUF };
    bf16* Vb[2] = { Ps + 2 * AT_HBUF, Ps + 4 * AT_HBUF };
    int bh = blockIdx.x;
    int b = bh >> 4, h = bh & 15;
    size_t bS = (size_t)b * SS;
    int q0 = blockIdx.y * 64;
    int tid = threadIdx.x, w = tid >> 5, lane = tid & 31;
    int gid = lane >> 2, tig = lane & 3;
    const int aRowOff = (lane & 15) * AT_STRIDE + 8 * (lane >> 4);
    const int bRowOff = (lane & 7) * AT_STRIDE + 8 * ((lane >> 3) & 1);

    const bf16* vbase = vt + ((size_t)(b * 1024 + h * 64)) * 1024;

    auto issue_tile = [&](int kt) {
        int kb0 = kt * 64;
        bf16* Ks = Kb[kt & 1];
        bf16* Vs = Vb[kt & 1];
#pragma unroll
        for (int e = 0; e < 4; e++) {
            int idx = tid + e * 128;
            int r = idx >> 3, q = idx & 7;
            cp16(&Ks[r * AT_STRIDE + q * 8],
                 qkv + (bS + kb0 + r) * 3072 + 1024 + h * 64 + q * 8);
            cp16(&Vs[r * AT_STRIDE + q * 8],
                 vbase + (size_t)r * 1024 + kb0 + q * 8);
        }
        asm volatile("cp.async.commit_group;");
    };

    issue_tile(0);

    {
        int q = tid >> 1, d0 = (tid & 1) * 32;
        const uint4* src = (const uint4*)(qkv + (bS + q0 + q) * 3072 + h * 64 + d0);
        uint4* dst = (uint4*)&Qs[q * AT_STRIDE + d0];
        dst[0] = src[0];
        dst[1] = src[1];
        dst[2] = src[2];
        dst[3] = src[3];
    }
    __syncthreads();

    unsigned qf[4][4];
#pragma unroll
    for (int kb4 = 0; kb4 < 4; kb4++)
        ldsm_x4(qf[kb4][0], qf[kb4][1], qf[kb4][2], qf[kb4][3],
                smaddr(&Qs[(w * 16) * AT_STRIDE + aRowOff + kb4 * 16]));

    float o[8][4];
#pragma unroll
    for (int nt = 0; nt < 8; nt++)
#pragma unroll
        for (int r = 0; r < 4; r++) o[nt][r] = 0.f;
    float mA = -1e30f, mB = -1e30f, lA = 0.f, lB = 0.f;

    for (int kt = 0; kt < 16; kt++) {
        asm volatile("cp.async.wait_group 0;" ::: "memory");
        __syncthreads();
        if (kt + 1 < 16) issue_tile(kt + 1);
        const bf16* Ks = Kb[kt & 1];
        const bf16* Vs = Vb[kt & 1];

        float s[8][4];
#pragma unroll
        for (int nt = 0; nt < 8; nt++)
#pragma unroll
            for (int r = 0; r < 4; r++) s[nt][r] = 0.f;
#pragma unroll
        for (int kb4 = 0; kb4 < 4; kb4++) {
#pragma unroll
            for (int nt = 0; nt < 8; nt++) {
                unsigned b0, b1;
                ldsm_x2(b0, b1, smaddr(&Ks[(nt * 8) * AT_STRIDE + bRowOff + kb4 * 16]));
                mma_bf16(s[nt], qf[kb4][0], qf[kb4][1], qf[kb4][2], qf[kb4][3], b0, b1);
            }
        }

        float tmA = -1e30f, tmB = -1e30f;
#pragma unroll
        for (int nt = 0; nt < 8; nt++) {
            tmA = fmaxf(tmA, fmaxf(s[nt][0], s[nt][1]));
            tmB = fmaxf(tmB, fmaxf(s[nt][2], s[nt][3]));
        }
        tmA = fmaxf(tmA, __shfl_xor_sync(0xffffffffu, tmA, 1));
        tmA = fmaxf(tmA, __shfl_xor_sync(0xffffffffu, tmA, 2));
        tmB = fmaxf(tmB, __shfl_xor_sync(0xffffffffu, tmB, 1));
        tmB = fmaxf(tmB, __shfl_xor_sync(0xffffffffu, tmB, 2));
        float nmA = fmaxf(mA, tmA), nmB = fmaxf(mB, tmB);
        float corrA = __expf(mA - nmA), corrB = __expf(mB - nmB);
        mA = nmA; mB = nmB;
        float sumA = 0.f, sumB = 0.f;
#pragma unroll
        for (int nt = 0; nt < 8; nt++) {
            s[nt][0] = __expf(s[nt][0] - nmA);
            s[nt][1] = __expf(s[nt][1] - nmA);
            s[nt][2] = __expf(s[nt][2] - nmB);
            s[nt][3] = __expf(s[nt][3] - nmB);
            sumA += s[nt][0] + s[nt][1];
            sumB += s[nt][2] + s[nt][3];
        }
        sumA += __shfl_xor_sync(0xffffffffu, sumA, 1);
        sumA += __shfl_xor_sync(0xffffffffu, sumA, 2);
        sumB += __shfl_xor_sync(0xffffffffu, sumB, 1);
        sumB += __shfl_xor_sync(0xffffffffu, sumB, 2);
        lA = lA * corrA + sumA;
        lB = lB * corrB + sumB;
#pragma unroll
        for (int nt = 0; nt < 8; nt++) {
            o[nt][0] *= corrA; o[nt][1] *= corrA;
            o[nt][2] *= corrB; o[nt][3] *= corrB;
        }
#pragma unroll
        for (int nt = 0; nt < 8; nt++) {
            int rq = w * 16 + gid;
            *(unsigned*)&Ps[rq * AT_STRIDE + nt * 8 + 2 * tig] = f2bf(s[nt][0], s[nt][1]);
            *(unsigned*)&Ps[(rq + 8) * AT_STRIDE + nt * 8 + 2 * tig] = f2bf(s[nt][2], s[nt][3]);
        }
        __syncwarp();

#pragma unroll
        for (int kc4 = 0; kc4 < 4; kc4++) {
            unsigned pf[4];
            ldsm_x4(pf[0], pf[1], pf[2], pf[3],
                    smaddr(&Ps[(w * 16) * AT_STRIDE + aRowOff + kc4 * 16]));
#pragma unroll
            for (int nt = 0; nt < 8; nt++) {
                unsigned b0, b1;
                ldsm_x2(b0, b1, smaddr(&Vs[(nt * 8) * AT_STRIDE + bRowOff + kc4 * 16]));
                mma_bf16(o[nt], pf[0], pf[1], pf[2], pf[3], b0, b1);
            }
        }
    }

    float invA = 1.0f / lA, invB = 1.0f / lB;
    size_t rowA = (bS + q0 + w * 16 + gid) * 1024 + h * 64;
    size_t rowB = (bS + q0 + w * 16 + gid + 8) * 1024 + h * 64;
#pragma unroll
    for (int nt = 0; nt < 8; nt++) {
        int col = nt * 8 + 2 * tig;
        *(unsigned*)&out[rowA + col] = f2bf(o[nt][0] * invA, o[nt][1] * invA);
        *(unsigned*)&out[rowB + col] = f2bf(o[nt][2] * invB, o[nt][3] * invB);
    }
}

// ---------------- launch ----------------
extern "C" void kernel_launch(void* const* d_in, const int* in_sizes, int n_in,
                              void* d_out, int out_size) {
    const float* x       = (const float*)d_in[0];
    const float* c       = (const float*)d_in[1];
    const float* norm1_w = (const float*)d_in[2];
    const float* norm2_w = (const float*)d_in[3];
    const float* w_qkv   = (const float*)d_in[4];
    const float* w_out   = (const float*)d_in[5];
    const float* w1      = (const float*)d_in[6];
    const float* b1      = (const float*)d_in[7];
    const float* w2      = (const float*)d_in[8];
    const float* b2      = (const float*)d_in[9];
    const float* adaLN_w = (const float*)d_in[10];
    const float* adaLN_b = (const float*)d_in[11];
    const float* cosb    = (const float*)d_in[12];
    const float* sinb    = (const float*)d_in[13];
    float* out = (float*)d_out;

    float *mod, *x1;
    bf16 *xm, *qkv, *attn, *hbuf, *vt, *wqkv_t, *wout_t, *w1_t, *w2_t;
    cudaGetSymbolAddress((void**)&mod,  g_mod);
    cudaGetSymbolAddress((void**)&xm,   g_xm);
    cudaGetSymbolAddress((void**)&qkv,  g_qkv);
    cudaGetSymbolAddress((void**)&attn, g_attn);
    cudaGetSymbolAddress((void**)&x1,   g_x1);
    cudaGetSymbolAddress((void**)&hbuf, g_h);
    cudaGetSymbolAddress((void**)&vt,   g_vt);
    cudaGetSymbolAddress((void**)&wqkv_t, g_wqkv_t);
    cudaGetSymbolAddress((void**)&wout_t, g_wout_t);
    cudaGetSymbolAddress((void**)&w1_t,   g_w1_t);
    cudaGetSymbolAddress((void**)&w2_t,   g_w2_t);

    cudaFuncSetAttribute(attn_mma_kernel, cudaFuncAttributeMaxDynamicSharedMemorySize,
                         AT_SMEM_BYTES);
    cudaFuncSetAttribute(tgemm<1>, cudaFuncAttributeMaxDynamicSharedMemorySize, TG_BYTES);
    cudaFuncSetAttribute(tgemm<2>, cudaFuncAttributeMaxDynamicSharedMemorySize, TG_BYTES);
    cudaFuncSetAttribute(tgemm<4>, cudaFuncAttributeMaxDynamicSharedMemorySize, TG_BYTES);

    const int PERSIST = 296;   // 148 SMs x 2 CTAs

    // 0) weights -> bf16 [N][K] transpose + adaLN mod vector (single launch)
    wtrans_all_kernel<<<3168, 256>>>(w_qkv, w_out, w1, w2,
                                     wqkv_t, wout_t, w1_t, w2_t,
                                     c, adaLN_w, adaLN_b, mod);

    // 1) LN1 + modulate
    ln_mod_kernel<<<BB * SS, 256>>>(x, norm1_w, mod, 0, 1, xm);

    // 2) QKV GEMM with fused RoPE -> bf16 qkv  (768 tiles, persistent)
    tgemm<4><<<PERSIST, 128, TG_BYTES>>>(
        xm, wqkv_t, nullptr, nullptr, nullptr, 0, cosb, sinb, qkv, BB * SS, 3 * DD, DD);

    // 3) V transpose -> vt
    vtrans_kernel<<<dim3(16, 16, 4), 256>>>(qkv, vt);

    // 4) attention -> bf16 attn
    attn_mma_kernel<<<dim3(BB * HH, SS / 64), 128, AT_SMEM_BYTES>>>(qkv, vt, attn);

    // 5) out-proj + gated residual -> fp32 x1  (256 tiles)
    tgemm<2><<<256, 128, TG_BYTES>>>(
        attn, wout_t, nullptr, x, mod, 2 * DD, nullptr, nullptr, x1, BB * SS, DD, DD);

    // 6) LN2 + modulate
    ln_mod_kernel<<<BB * SS, 256>>>(x1, norm2_w, mod, 3, 4, xm);

    // 7) MLP up + GELU -> bf16 h  (1024 tiles, persistent)
    tgemm<1><<<PERSIST, 128, TG_BYTES>>>(
        xm, w1_t, b1, nullptr, nullptr, 0, nullptr, nullptr, hbuf, BB * SS, MLPD, DD);

    // 8) MLP down + gated residual -> fp32 out  (256 tiles)
    tgemm<2><<<256, 128, TG_BYTES>>>(
        hbuf, w2_t, b2, x1, mod, 5 * DD, nullptr, nullptr, out, BB * SS, DD, MLPD);
}

// round 16
// speedup vs baseline: 1.1294x; 1.0055x over previous
#include <cuda_runtime.h>
#include <cuda_bf16.h>
#include <cstdint>
#include <math.h>

// Problem constants
#define BB 4
#define SS 1024
#define DD 1024
#define HH 16
#define HD 64
#define MLPD 4096
#define MODW 6144   // 6*D
#define LN_EPS 1e-5f

typedef __nv_bfloat16 bf16;
typedef __nv_bfloat162 bf162;

// ---------------- scratch (no allocs allowed) ----------------
__device__ float g_mod[BB * MODW];
__device__ bf16  g_xm[(size_t)BB * SS * DD];
__device__ bf16  g_qkv[(size_t)BB * SS * 3 * DD];        // bf16; q,k roped at GEMM epilogue
__device__ bf16  g_attn[(size_t)BB * SS * DD];
__device__ float g_x1[(size_t)BB * SS * DD];
__device__ bf16  g_h[(size_t)BB * SS * MLPD];
// transposed bf16 weights [N][K]
__device__ bf16 g_wqkv_t[(size_t)3 * DD * DD];
__device__ bf16 g_wout_t[(size_t)DD * DD];
__device__ bf16 g_w1_t[(size_t)MLPD * DD];
__device__ bf16 g_w2_t[(size_t)DD * MLPD];

// ---------------- helpers ----------------
__device__ __forceinline__ unsigned smaddr(const void* p) {
    return (unsigned)__cvta_generic_to_shared(p);
}
__device__ __forceinline__ void ldsm_x4(unsigned& r0, unsigned& r1, unsigned& r2,
                                        unsigned& r3, unsigned a) {
    asm volatile("ldmatrix.sync.aligned.m8n8.x4.shared.b16 {%0,%1,%2,%3},[%4];"
                 : "=r"(r0), "=r"(r1), "=r"(r2), "=r"(r3) : "r"(a));
}
__device__ __forceinline__ void ldsm_x2(unsigned& r0, unsigned& r1, unsigned a) {
    asm volatile("ldmatrix.sync.aligned.m8n8.x2.shared.b16 {%0,%1},[%2];"
                 : "=r"(r0), "=r"(r1) : "r"(a));
}
__device__ __forceinline__ void ldsm_x2t(unsigned& r0, unsigned& r1, unsigned a) {
    asm volatile("ldmatrix.sync.aligned.m8n8.x2.trans.shared.b16 {%0,%1},[%2];"
                 : "=r"(r0), "=r"(r1) : "r"(a));
}
__device__ __forceinline__ void mma_bf16(float c[4], unsigned a0, unsigned a1,
                                         unsigned a2, unsigned a3,
                                         unsigned b0, unsigned b1) {
    asm volatile("mma.sync.aligned.m16n8k16.row.col.f32.bf16.bf16.f32 "
                 "{%0,%1,%2,%3}, {%4,%5,%6,%7}, {%8,%9}, {%0,%1,%2,%3};"
                 : "+f"(c[0]), "+f"(c[1]), "+f"(c[2]), "+f"(c[3])
                 : "r"(a0), "r"(a1), "r"(a2), "r"(a3), "r"(b0), "r"(b1));
}
__device__ __forceinline__ void cp16(void* s, const void* g) {
    asm volatile("cp.async.cg.shared.global [%0], [%1], 16;"
                 :: "r"(smaddr(s)), "l"(g));
}
__device__ __forceinline__ unsigned f2bf(float x, float y) {
    bf162 t = __floats2bfloat162_rn(x, y);
    return *(unsigned*)&t;
}

// ---------------- merged weight transpose (64x64 uint4) + adaLN mod -----------
// 64x64 tiles: wqkv 768, wout 256, w1 1024, w2 1024 -> [0,3072); mod [3072,3168)
__global__ __launch_bounds__(256)
void wtrans_all_kernel(const float* __restrict__ s0, const float* __restrict__ s1,
                       const float* __restrict__ s2, const float* __restrict__ s3,
                       bf16* __restrict__ d0, bf16* __restrict__ d1,
                       bf16* __restrict__ d2, bf16* __restrict__ d3,
                       const float* __restrict__ c, const float* __restrict__ aw,
                       const float* __restrict__ ab, float* __restrict__ mod) {
    __shared__ float t[64][68];
    int tb = blockIdx.x;
    int tid = threadIdx.x;
    if (tb >= 3072) {
        int n = (tb - 3072) * 256 + tid;                // [0, 24576)
        int b = n / MODW;
        int col = n - b * MODW;
        float acc = ab[col];
        const float* cb = c + b * 128;
#pragma unroll 8
        for (int k = 0; k < 128; k++) acc = fmaf(cb[k], aw[(size_t)k * MODW + col], acc);
        mod[n] = acc;
        return;
    }
    const float* src; bf16* dst; int K, N;
    if (tb < 768)       { src = s0; dst = d0; K = 1024; N = 3072; }
    else if (tb < 1024) { tb -= 768;  src = s1; dst = d1; K = 1024; N = 1024; }
    else if (tb < 2048) { tb -= 1024; src = s2; dst = d2; K = 1024; N = 4096; }
    else                { tb -= 2048; src = s3; dst = d3; K = 4096; N = 1024; }
    int ntn = N >> 6;
    int k0 = (tb / ntn) * 64, n0 = (tb % ntn) * 64;
#pragma unroll
    for (int e = 0; e < 4; e++) {
        int idx = tid + e * 256;                        // [0,1024)
        int row = idx >> 4, q = idx & 15;
        *(float4*)&t[row][q * 4] =
            *(const float4*)(src + (size_t)(k0 + row) * N + n0 + q * 4);
    }
    __syncthreads();
#pragma unroll
    for (int e = 0; e < 2; e++) {
        int idx = tid + e * 256;                        // [0,512)
        int j = idx & 63, q = idx >> 6;
        bf16 v[8];
#pragma unroll
        for (int i = 0; i < 8; i++) v[i] = __float2bfloat16_rn(t[q * 8 + i][j]);
        *(uint4*)(dst + (size_t)(n0 + j) * K + k0 + q * 8) = *(uint4*)v;
    }
}

// ---------------- fused LayerNorm + modulate (vectorized, bf16 out) -----------
__global__ __launch_bounds__(256)
void ln_mod_kernel(const float* __restrict__ x, const float* __restrict__ w,
                   const float* __restrict__ mod, int shiftSeg, int scaleSeg,
                   bf16* __restrict__ out) {
    __shared__ float r1[8], r2[8];
    int row = blockIdx.x;
    int b = row >> 10;
    int tid = threadIdx.x, lane = tid & 31, wrp = tid >> 5;
    float4 v = ((const float4*)(x + (size_t)row * DD))[tid];
    float s = v.x + v.y + v.z + v.w;
    float ss = v.x * v.x + v.y * v.y + v.z * v.z + v.w * v.w;
#pragma unroll
    for (int o = 16; o > 0; o >>= 1) {
        s  += __shfl_xor_sync(0xffffffffu, s, o);
        ss += __shfl_xor_sync(0xffffffffu, ss, o);
    }
    if (lane == 0) { r1[wrp] = s; r2[wrp] = ss; }
    __syncthreads();
    if (wrp == 0) {
        float a = (lane < 8) ? r1[lane] : 0.f;
        float c2 = (lane < 8) ? r2[lane] : 0.f;
#pragma unroll
        for (int o = 4; o > 0; o >>= 1) {
            a  += __shfl_xor_sync(0xffffffffu, a, o);
            c2 += __shfl_xor_sync(0xffffffffu, c2, o);
        }
        if (lane == 0) { r1[0] = a; r2[0] = c2; }
    }
    __syncthreads();
    float mu = r1[0] * (1.0f / DD);
    float var = r2[0] * (1.0f / DD) - mu * mu;
    float rstd = rsqrtf(var + LN_EPS);
    float4 wv = ((const float4*)w)[tid];
    float4 sh = ((const float4*)(mod + (size_t)b * MODW + shiftSeg * DD))[tid];
    float4 sc = ((const float4*)(mod + (size_t)b * MODW + scaleSeg * DD))[tid];
    float y0 = fmaf((v.x - mu) * rstd * wv.x, 1.0f + sc.x, sh.x);
    float y1 = fmaf((v.y - mu) * rstd * wv.y, 1.0f + sc.y, sh.y);
    float y2 = fmaf((v.z - mu) * rstd * wv.z, 1.0f + sc.z, sh.z);
    float y3 = fmaf((v.w - mu) * rstd * wv.w, 1.0f + sc.w, sh.w);
    uint2 o2 = make_uint2(f2bf(y0, y1), f2bf(y2, y3));
    *(uint2*)(out + (size_t)row * DD + tid * 4) = o2;
}

__device__ __forceinline__ float gelu_tanh(float x) {
    float x3 = x * x * x;
    return 0.5f * x * (1.0f + tanhf(0.7978845608028654f * (x + 0.044715f * x3)));
}

// ---------------- bf16 tensor-core GEMM: persistent tiles ---------------------
#define TG_STRIDE 40
#define TG_HBUF (128 * TG_STRIDE)
#define TG_STAGE (2 * TG_HBUF)
#define TG_BYTES (4 * TG_STAGE * 2)              // 81920 B

template<int EPI>
__global__ __launch_bounds__(128, 2)
void tgemm(const bf16* __restrict__ A, const bf16* __restrict__ Bt,
           const float* __restrict__ bias, const float* __restrict__ resid,
           const float* __restrict__ mod, int modOff,
           const float* __restrict__ cosb, const float* __restrict__ sinb,
           void* __restrict__ Cv, int M, int N, int K) {
    extern __shared__ bf16 smh[];
    const int tid = threadIdx.x;
    const int lane = tid & 31, wid = tid >> 5;
    const int gid = lane >> 2, tig = lane & 3;
    const int m0w = (wid & 1) * 64;
    const int n0w = (wid >> 1) * 64;
    const int aRowOff = (lane & 15) * TG_STRIDE + 8 * (lane >> 4);
    const int bRowOff = (lane & 7) * TG_STRIDE + 8 * ((lane >> 3) & 1);
    const int NS = K >> 5;
    const int ntx = N >> 7;
    const int totalTiles = (M >> 7) * ntx;

    for (int tile = blockIdx.x; tile < totalTiles; tile += gridDim.x) {
        const int bx = tile % ntx, by = tile / ntx;
        const bf16* Ag = A + (size_t)(by * 128) * K;
        const bf16* Bg = Bt + (size_t)(bx * 128) * K;

        float acc[4][8][4];
#pragma unroll
        for (int i = 0; i < 4; i++)
#pragma unroll
            for (int j = 0; j < 8; j++)
#pragma unroll
                for (int r = 0; r < 4; r++) acc[i][j][r] = 0.f;

        auto issue = [&](int ks) {
            bf16* As = smh + (ks & 3) * TG_STAGE;
            bf16* Bs = As + TG_HBUF;
#pragma unroll
            for (int e = 0; e < 4; e++) {
                int idx = tid + e * 128;
                int row = idx >> 2, q = idx & 3;
                cp16(&As[row * TG_STRIDE + q * 8], Ag + (size_t)row * K + ks * 32 + q * 8);
            }
#pragma unroll
            for (int e = 0; e < 4; e++) {
                int idx = tid + e * 128;
                int row = idx >> 2, q = idx & 3;
                cp16(&Bs[row * TG_STRIDE + q * 8], Bg + (size_t)row * K + ks * 32 + q * 8);
            }
            asm volatile("cp.async.commit_group;");
        };

        issue(0); issue(1); issue(2);

        for (int ks = 0; ks < NS; ks++) {
            if (ks + 2 < NS) asm volatile("cp.async.wait_group 2;" ::: "memory");
            else             asm volatile("cp.async.wait_group 0;" ::: "memory");
            __syncthreads();
            if (ks + 3 < NS) issue(ks + 3);
            const bf16* As = smh + (ks & 3) * TG_STAGE;
            const bf16* Bs = As + TG_HBUF;

            unsigned afA[4][4], bfA[8][2], afB[4][4], bfB[8][2];
#pragma unroll
            for (int mt = 0; mt < 4; mt++)
                ldsm_x4(afA[mt][0], afA[mt][1], afA[mt][2], afA[mt][3],
                        smaddr(&As[(m0w + mt * 16) * TG_STRIDE + aRowOff]));
#pragma unroll
            for (int nt = 0; nt < 8; nt++)
                ldsm_x2(bfA[nt][0], bfA[nt][1],
                        smaddr(&Bs[(n0w + nt * 8) * TG_STRIDE + bRowOff]));
#pragma unroll
            for (int mt = 0; mt < 4; mt++)
                ldsm_x4(afB[mt][0], afB[mt][1], afB[mt][2], afB[mt][3],
                        smaddr(&As[(m0w + mt * 16) * TG_STRIDE + aRowOff + 16]));
#pragma unroll
            for (int nt = 0; nt < 8; nt++)
                ldsm_x2(bfB[nt][0], bfB[nt][1],
                        smaddr(&Bs[(n0w + nt * 8) * TG_STRIDE + bRowOff + 16]));

#pragma unroll
            for (int mt = 0; mt < 4; mt++)
#pragma unroll
                for (int nt = 0; nt < 8; nt++)
                    mma_bf16(acc[mt][nt], afA[mt][0], afA[mt][1], afA[mt][2], afA[mt][3],
                             bfA[nt][0], bfA[nt][1]);
#pragma unroll
            for (int mt = 0; mt < 4; mt++)
#pragma unroll
                for (int nt = 0; nt < 8; nt++)
                    mma_bf16(acc[mt][nt], afB[mt][0], afB[mt][1], afB[mt][2], afB[mt][3],
                             bfB[nt][0], bfB[nt][1]);
        }
        __syncthreads();   // all smem reads done before next tile's prologue

        // ---- epilogue ----
        if (EPI == 4) {
            int colBase = bx * 128 + n0w;          // warp-uniform, 64-aligned
            int sel = colBase >> 10;               // 0=q, 1=k, 2=v
            bf16* C = (bf16*)Cv;
            if (sel == 2) {
#pragma unroll
                for (int mt = 0; mt < 4; mt++)
#pragma unroll
                    for (int half = 0; half < 2; half++) {
                        int row = by * 128 + m0w + mt * 16 + gid + 8 * half;
                        size_t rowBase = (size_t)row * N;
#pragma unroll
                        for (int nt = 0; nt < 8; nt++) {
                            int col = colBase + nt * 8 + 2 * tig;
                            *(unsigned*)&C[rowBase + col] =
                                f2bf(acc[mt][nt][2 * half], acc[mt][nt][2 * half + 1]);
                        }
                    }
            } else {
                float scale = sel ? 1.0f : 0.125f;
#pragma unroll
                for (int mt = 0; mt < 4; mt++)
#pragma unroll
                    for (int half = 0; half < 2; half++) {
                        int row = by * 128 + m0w + mt * 16 + gid + 8 * half;
                        int s = row & (SS - 1);
                        size_t rowBase = (size_t)row * N;
#pragma unroll
                        for (int nt = 0; nt < 4; nt++) {
                            int e0 = nt * 8 + 2 * tig;
                            float c0 = cosb[s * 32 + e0], c1 = cosb[s * 32 + e0 + 1];
                            float sv0 = sinb[s * 32 + e0], sv1 = sinb[s * 32 + e0 + 1];
                            float t1a = acc[mt][nt][2 * half];
                            float t1b = acc[mt][nt][2 * half + 1];
                            float t2a = acc[mt][nt + 4][2 * half];
                            float t2b = acc[mt][nt + 4][2 * half + 1];
                            int col = colBase + e0;
                            *(unsigned*)&C[rowBase + col] =
                                f2bf((t1a * c0 - t2a * sv0) * scale,
                                     (t1b * c1 - t2b * sv1) * scale);
                            *(unsigned*)&C[rowBase + col + 32] =
                                f2bf((t2a * c0 + t1a * sv0) * scale,
                                     (t2b * c1 + t1b * sv1) * scale);
                        }
                    }
            }
        } else {
#pragma unroll
            for (int mt = 0; mt < 4; mt++) {
#pragma unroll
                for (int half = 0; half < 2; half++) {
                    int row = by * 128 + m0w + mt * 16 + gid + 8 * half;
                    size_t rowBase = (size_t)row * N;
#pragma unroll
                    for (int nt = 0; nt < 8; nt++) {
                        int col = bx * 128 + n0w + nt * 8 + 2 * tig;
                        float v0 = acc[mt][nt][2 * half];
                        float v1 = acc[mt][nt][2 * half + 1];
                        if (EPI == 1) {
                            v0 = gelu_tanh(v0 + bias[col]);
                            v1 = gelu_tanh(v1 + bias[col + 1]);
                            *(unsigned*)&((bf16*)Cv)[rowBase + col] = f2bf(v0, v1);
                        } else if (EPI == 2) {
                            if (bias) { v0 += bias[col]; v1 += bias[col + 1]; }
                            size_t mb = (size_t)(row >> 10) * MODW + modOff + col;
                            float g0 = mod[mb], g1 = mod[mb + 1];
                            float2 rr = *(const float2*)&resid[rowBase + col];
                            *(float2*)&((float*)Cv)[rowBase + col] =
                                make_float2(fmaf(g0, v0, rr.x), fmaf(g1, v1, rr.y));
                        } else {
                            *(unsigned*)&((bf16*)Cv)[rowBase + col] = f2bf(v0, v1);
                        }
                    }
                }
            }
        }
    }
}

// ---------------- attention: flash, bf16 mma; V staged [key][d], ldmatrix.trans
#define AT_STRIDE 72
#define AT_HBUF (64 * AT_STRIDE)
#define AT_SMEM_BYTES (6 * AT_HBUF * 2)          // 55296 B

__global__ __launch_bounds__(128, 3)
void attn_mma_kernel(const bf16* __restrict__ qkv, bf16* __restrict__ out) {
    extern __shared__ bf16 smh[];
    bf16* Qs = smh;
    bf16* Ps = Qs + AT_HBUF;
    bf16* Kb[2] = { Ps + AT_HBUF, Ps + 3 * AT_HBUF };
    bf16* Vb[2] = { Ps + 2 * AT_HBUF, Ps + 4 * AT_HBUF };
    int bh = blockIdx.x;
    int b = bh >> 4, h = bh & 15;
    size_t bS = (size_t)b * SS;
    int q0 = blockIdx.y * 64;
    int tid = threadIdx.x, w = tid >> 5, lane = tid & 31;
    int gid = lane >> 2, tig = lane & 3;
    const int aRowOff = (lane & 15) * AT_STRIDE + 8 * (lane >> 4);
    const int bRowOff = (lane & 7) * AT_STRIDE + 8 * ((lane >> 3) & 1);
    const int vRowOff = (lane & 7) + 8 * ((lane >> 3) & 1);   // row index for trans loads

    auto issue_tile = [&](int kt) {
        int kb0 = kt * 64;
        bf16* Ks = Kb[kt & 1];
        bf16* Vs = Vb[kt & 1];
#pragma unroll
        for (int e = 0; e < 4; e++) {
            int idx = tid + e * 128;
            int r = idx >> 3, q = idx & 7;
            cp16(&Ks[r * AT_STRIDE + q * 8],
                 qkv + (bS + kb0 + r) * 3072 + 1024 + h * 64 + q * 8);
            cp16(&Vs[r * AT_STRIDE + q * 8],
                 qkv + (bS + kb0 + r) * 3072 + 2048 + h * 64 + q * 8);   // V [key][d]
        }
        asm volatile("cp.async.commit_group;");
    };

    issue_tile(0);

    {
        int q = tid >> 1, d0 = (tid & 1) * 32;
        const uint4* src = (const uint4*)(qkv + (bS + q0 + q) * 3072 + h * 64 + d0);
        uint4* dst = (uint4*)&Qs[q * AT_STRIDE + d0];
        dst[0] = src[0];
        dst[1] = src[1];
        dst[2] = src[2];
        dst[3] = src[3];
    }
    __syncthreads();

    unsigned qf[4][4];
#pragma unroll
    for (int kb4 = 0; kb4 < 4; kb4++)
        ldsm_x4(qf[kb4][0], qf[kb4][1], qf[kb4][2], qf[kb4][3],
                smaddr(&Qs[(w * 16) * AT_STRIDE + aRowOff + kb4 * 16]));

    float o[8][4];
#pragma unroll
    for (int nt = 0; nt < 8; nt++)
#pragma unroll
        for (int r = 0; r < 4; r++) o[nt][r] = 0.f;
    float mA = -1e30f, mB = -1e30f, lA = 0.f, lB = 0.f;

    for (int kt = 0; kt < 16; kt++) {
        asm volatile("cp.async.wait_group 0;" ::: "memory");
        __syncthreads();
        if (kt + 1 < 16) issue_tile(kt + 1);
        const bf16* Ks = Kb[kt & 1];
        const bf16* Vs = Vb[kt & 1];

        // ---- QK^T ----
        float s[8][4];
#pragma unroll
        for (int nt = 0; nt < 8; nt++)
#pragma unroll
            for (int r = 0; r < 4; r++) s[nt][r] = 0.f;
#pragma unroll
        for (int kb4 = 0; kb4 < 4; kb4++) {
#pragma unroll
            for (int nt = 0; nt < 8; nt++) {
                unsigned b0, b1;
                ldsm_x2(b0, b1, smaddr(&Ks[(nt * 8) * AT_STRIDE + bRowOff + kb4 * 16]));
                mma_bf16(s[nt], qf[kb4][0], qf[kb4][1], qf[kb4][2], qf[kb4][3], b0, b1);
            }
        }

        // ---- online softmax (rows gid, gid+8) ----
        float tmA = -1e30f, tmB = -1e30f;
#pragma unroll
        for (int nt = 0; nt < 8; nt++) {
            tmA = fmaxf(tmA, fmaxf(s[nt][0], s[nt][1]));
            tmB = fmaxf(tmB, fmaxf(s[nt][2], s[nt][3]));
        }
        tmA = fmaxf(tmA, __shfl_xor_sync(0xffffffffu, tmA, 1));
        tmA = fmaxf(tmA, __shfl_xor_sync(0xffffffffu, tmA, 2));
        tmB = fmaxf(tmB, __shfl_xor_sync(0xffffffffu, tmB, 1));
        tmB = fmaxf(tmB, __shfl_xor_sync(0xffffffffu, tmB, 2));
        float nmA = fmaxf(mA, tmA), nmB = fmaxf(mB, tmB);
        float corrA = __expf(mA - nmA), corrB = __expf(mB - nmB);
        mA = nmA; mB = nmB;
        float sumA = 0.f, sumB = 0.f;
#pragma unroll
        for (int nt = 0; nt < 8; nt++) {
            s[nt][0] = __expf(s[nt][0] - nmA);
            s[nt][1] = __expf(s[nt][1] - nmA);
            s[nt][2] = __expf(s[nt][2] - nmB);
            s[nt][3] = __expf(s[nt][3] - nmB);
            sumA += s[nt][0] + s[nt][1];
            sumB += s[nt][2] + s[nt][3];
        }
        sumA += __shfl_xor_sync(0xffffffffu, sumA, 1);
        sumA += __shfl_xor_sync(0xffffffffu, sumA, 2);
        sumB += __shfl_xor_sync(0xffffffffu, sumB, 1);
        sumB += __shfl_xor_sync(0xffffffffu, sumB, 2);
        lA = lA * corrA + sumA;
        lB = lB * corrB + sumB;
#pragma unroll
        for (int nt = 0; nt < 8; nt++) {
            o[nt][0] *= corrA; o[nt][1] *= corrA;
            o[nt][2] *= corrB; o[nt][3] *= corrB;
        }
#pragma unroll
        for (int nt = 0; nt < 8; nt++) {
            int rq = w * 16 + gid;
            *(unsigned*)&Ps[rq * AT_STRIDE + nt * 8 + 2 * tig] = f2bf(s[nt][0], s[nt][1]);
            *(unsigned*)&Ps[(rq + 8) * AT_STRIDE + nt * 8 + 2 * tig] = f2bf(s[nt][2], s[nt][3]);
        }
        __syncwarp();

        // ---- PV: B-fragments from V [key][d] via ldmatrix.trans ----
#pragma unroll
        for (int kc4 = 0; kc4 < 4; kc4++) {
            unsigned pf[4];
            ldsm_x4(pf[0], pf[1], pf[2], pf[3],
                    smaddr(&Ps[(w * 16) * AT_STRIDE + aRowOff + kc4 * 16]));
#pragma unroll
            for (int nt = 0; nt < 8; nt++) {
                unsigned b0, b1;
                ldsm_x2t(b0, b1,
                         smaddr(&Vs[(kc4 * 16 + vRowOff) * AT_STRIDE + nt * 8]));
                mma_bf16(o[nt], pf[0], pf[1], pf[2], pf[3], b0, b1);
            }
        }
    }

    float invA = 1.0f / lA, invB = 1.0f / lB;
    size_t rowA = (bS + q0 + w * 16 + gid) * 1024 + h * 64;
    size_t rowB = (bS + q0 + w * 16 + gid + 8) * 1024 + h * 64;
#pragma unroll
    for (int nt = 0; nt < 8; nt++) {
        int col = nt * 8 + 2 * tig;
        *(unsigned*)&out[rowA + col] = f2bf(o[nt][0] * invA, o[nt][1] * invA);
        *(unsigned*)&out[rowB + col] = f2bf(o[nt][2] * invB, o[nt][3] * invB);
    }
}

// ---------------- launch ----------------
extern "C" void kernel_launch(void* const* d_in, const int* in_sizes, int n_in,
                              void* d_out, int out_size) {
    const float* x       = (const float*)d_in[0];
    const float* c       = (const float*)d_in[1];
    const float* norm1_w = (const float*)d_in[2];
    const float* norm2_w = (const float*)d_in[3];
    const float* w_qkv   = (const float*)d_in[4];
    const float* w_out   = (const float*)d_in[5];
    const float* w1      = (const float*)d_in[6];
    const float* b1      = (const float*)d_in[7];
    const float* w2      = (const float*)d_in[8];
    const float* b2      = (const float*)d_in[9];
    const float* adaLN_w = (const float*)d_in[10];
    const float* adaLN_b = (const float*)d_in[11];
    const float* cosb    = (const float*)d_in[12];
    const float* sinb    = (const float*)d_in[13];
    float* out = (float*)d_out;

    float *mod, *x1;
    bf16 *xm, *qkv, *attn, *hbuf, *wqkv_t, *wout_t, *w1_t, *w2_t;
    cudaGetSymbolAddress((void**)&mod,  g_mod);
    cudaGetSymbolAddress((void**)&xm,   g_xm);
    cudaGetSymbolAddress((void**)&qkv,  g_qkv);
    cudaGetSymbolAddress((void**)&attn, g_attn);
    cudaGetSymbolAddress((void**)&x1,   g_x1);
    cudaGetSymbolAddress((void**)&hbuf, g_h);
    cudaGetSymbolAddress((void**)&wqkv_t, g_wqkv_t);
    cudaGetSymbolAddress((void**)&wout_t, g_wout_t);
    cudaGetSymbolAddress((void**)&w1_t,   g_w1_t);
    cudaGetSymbolAddress((void**)&w2_t,   g_w2_t);

    cudaFuncSetAttribute(attn_mma_kernel, cudaFuncAttributeMaxDynamicSharedMemorySize,
                         AT_SMEM_BYTES);
    cudaFuncSetAttribute(tgemm<1>, cudaFuncAttributeMaxDynamicSharedMemorySize, TG_BYTES);
    cudaFuncSetAttribute(tgemm<2>, cudaFuncAttributeMaxDynamicSharedMemorySize, TG_BYTES);
    cudaFuncSetAttribute(tgemm<4>, cudaFuncAttributeMaxDynamicSharedMemorySize, TG_BYTES);

    const int PERSIST = 296;   // 148 SMs x 2 CTAs

    // 0) weights -> bf16 [N][K] transpose + adaLN mod vector (single launch)
    wtrans_all_kernel<<<3168, 256>>>(w_qkv, w_out, w1, w2,
                                     wqkv_t, wout_t, w1_t, w2_t,
                                     c, adaLN_w, adaLN_b, mod);

    // 1) LN1 + modulate
    ln_mod_kernel<<<BB * SS, 256>>>(x, norm1_w, mod, 0, 1, xm);

    // 2) QKV GEMM with fused RoPE -> bf16 qkv  (768 tiles, persistent)
    tgemm<4><<<PERSIST, 128, TG_BYTES>>>(
        xm, wqkv_t, nullptr, nullptr, nullptr, 0, cosb, sinb, qkv, BB * SS, 3 * DD, DD);

    // 3) attention (V via ldmatrix.trans, no transpose pass) -> bf16 attn
    attn_mma_kernel<<<dim3(BB * HH, SS / 64), 128, AT_SMEM_BYTES>>>(qkv, attn);

    // 4) out-proj + gated residual -> fp32 x1  (256 tiles)
    tgemm<2><<<256, 128, TG_BYTES>>>(
        attn, wout_t, nullptr, x, mod, 2 * DD, nullptr, nullptr, x1, BB * SS, DD, DD);

    // 5) LN2 + modulate
    ln_mod_kernel<<<BB * SS, 256>>>(x1, norm2_w, mod, 3, 4, xm);

    // 6) MLP up + GELU -> bf16 h  (1024 tiles, persistent)
    tgemm<1><<<PERSIST, 128, TG_BYTES>>>(
        xm, w1_t, b1, nullptr, nullptr, 0, nullptr, nullptr, hbuf, BB * SS, MLPD, DD);

    // 7) MLP down + gated residual -> fp32 out  (256 tiles)
    tgemm<2><<<256, 128, TG_BYTES>>>(
        hbuf, w2_t, b2, x1, mod, 5 * DD, nullptr, nullptr, out, BB * SS, DD, MLPD);
}

// round 17
// speedup vs baseline: 1.1373x; 1.0069x over previous
#include <cuda_runtime.h>
#include <cuda_bf16.h>
#include <cstdint>
#include <math.h>

// Problem constants
#define BB 4
#define SS 1024
#define DD 1024
#define HH 16
#define HD 64
#define MLPD 4096
#define MODW 6144   // 6*D
#define LN_EPS 1e-5f

typedef __nv_bfloat16 bf16;
typedef __nv_bfloat162 bf162;

// ---------------- scratch (no allocs allowed) ----------------
__device__ float g_mod[BB * MODW];
__device__ bf16  g_xm[(size_t)BB * SS * DD];
__device__ bf16  g_qkv[(size_t)BB * SS * 3 * DD];        // bf16; q,k roped at GEMM epilogue
__device__ bf16  g_attn[(size_t)BB * SS * DD];
__device__ float g_x1[(size_t)BB * SS * DD];
__device__ bf16  g_h[(size_t)BB * SS * MLPD];
// transposed bf16 weights [N][K]
__device__ bf16 g_wqkv_t[(size_t)3 * DD * DD];
__device__ bf16 g_wout_t[(size_t)DD * DD];
__device__ bf16 g_w1_t[(size_t)MLPD * DD];
__device__ bf16 g_w2_t[(size_t)DD * MLPD];

// ---------------- helpers ----------------
__device__ __forceinline__ unsigned smaddr(const void* p) {
    return (unsigned)__cvta_generic_to_shared(p);
}
__device__ __forceinline__ void ldsm_x4(unsigned& r0, unsigned& r1, unsigned& r2,
                                        unsigned& r3, unsigned a) {
    asm volatile("ldmatrix.sync.aligned.m8n8.x4.shared.b16 {%0,%1,%2,%3},[%4];"
                 : "=r"(r0), "=r"(r1), "=r"(r2), "=r"(r3) : "r"(a));
}
__device__ __forceinline__ void ldsm_x2(unsigned& r0, unsigned& r1, unsigned a) {
    asm volatile("ldmatrix.sync.aligned.m8n8.x2.shared.b16 {%0,%1},[%2];"
                 : "=r"(r0), "=r"(r1) : "r"(a));
}
__device__ __forceinline__ void ldsm_x2t(unsigned& r0, unsigned& r1, unsigned a) {
    asm volatile("ldmatrix.sync.aligned.m8n8.x2.trans.shared.b16 {%0,%1},[%2];"
                 : "=r"(r0), "=r"(r1) : "r"(a));
}
__device__ __forceinline__ void mma_bf16(float c[4], unsigned a0, unsigned a1,
                                         unsigned a2, unsigned a3,
                                         unsigned b0, unsigned b1) {
    asm volatile("mma.sync.aligned.m16n8k16.row.col.f32.bf16.bf16.f32 "
                 "{%0,%1,%2,%3}, {%4,%5,%6,%7}, {%8,%9}, {%0,%1,%2,%3};"
                 : "+f"(c[0]), "+f"(c[1]), "+f"(c[2]), "+f"(c[3])
                 : "r"(a0), "r"(a1), "r"(a2), "r"(a3), "r"(b0), "r"(b1));
}
__device__ __forceinline__ void cp16(void* s, const void* g) {
    asm volatile("cp.async.cg.shared.global [%0], [%1], 16;"
                 :: "r"(smaddr(s)), "l"(g));
}
__device__ __forceinline__ unsigned f2bf(float x, float y) {
    bf162 t = __floats2bfloat162_rn(x, y);
    return *(unsigned*)&t;
}

// ---------------- merged weight transpose (64x64 uint4) + adaLN mod -----------
// 64x64 tiles: wqkv 768, wout 256, w1 1024, w2 1024 -> [0,3072); mod [3072,3168)
__global__ __launch_bounds__(256)
void wtrans_all_kernel(const float* __restrict__ s0, const float* __restrict__ s1,
                       const float* __restrict__ s2, const float* __restrict__ s3,
                       bf16* __restrict__ d0, bf16* __restrict__ d1,
                       bf16* __restrict__ d2, bf16* __restrict__ d3,
                       const float* __restrict__ c, const float* __restrict__ aw,
                       const float* __restrict__ ab, float* __restrict__ mod) {
    __shared__ float t[64][68];
    int tb = blockIdx.x;
    int tid = threadIdx.x;
    if (tb >= 3072) {
        int n = (tb - 3072) * 256 + tid;                // [0, 24576)
        int b = n / MODW;
        int col = n - b * MODW;
        float acc = ab[col];
        const float* cb = c + b * 128;
#pragma unroll 8
        for (int k = 0; k < 128; k++) acc = fmaf(cb[k], aw[(size_t)k * MODW + col], acc);
        mod[n] = acc;
        return;
    }
    const float* src; bf16* dst; int K, N;
    if (tb < 768)       { src = s0; dst = d0; K = 1024; N = 3072; }
    else if (tb < 1024) { tb -= 768;  src = s1; dst = d1; K = 1024; N = 1024; }
    else if (tb < 2048) { tb -= 1024; src = s2; dst = d2; K = 1024; N = 4096; }
    else                { tb -= 2048; src = s3; dst = d3; K = 4096; N = 1024; }
    int ntn = N >> 6;
    int k0 = (tb / ntn) * 64, n0 = (tb % ntn) * 64;
#pragma unroll
    for (int e = 0; e < 4; e++) {
        int idx = tid + e * 256;                        // [0,1024)
        int row = idx >> 4, q = idx & 15;
        *(float4*)&t[row][q * 4] =
            *(const float4*)(src + (size_t)(k0 + row) * N + n0 + q * 4);
    }
    __syncthreads();
#pragma unroll
    for (int e = 0; e < 2; e++) {
        int idx = tid + e * 256;                        // [0,512)
        int j = idx & 63, q = idx >> 6;
        bf16 v[8];
#pragma unroll
        for (int i = 0; i < 8; i++) v[i] = __float2bfloat16_rn(t[q * 8 + i][j]);
        *(uint4*)(dst + (size_t)(n0 + j) * K + k0 + q * 8) = *(uint4*)v;
    }
}

// ---------------- fused LayerNorm + modulate (vectorized, bf16 out) -----------
__global__ __launch_bounds__(256)
void ln_mod_kernel(const float* __restrict__ x, const float* __restrict__ w,
                   const float* __restrict__ mod, int shiftSeg, int scaleSeg,
                   bf16* __restrict__ out) {
    __shared__ float r1[8], r2[8];
    int row = blockIdx.x;
    int b = row >> 10;
    int tid = threadIdx.x, lane = tid & 31, wrp = tid >> 5;
    float4 v = ((const float4*)(x + (size_t)row * DD))[tid];
    float s = v.x + v.y + v.z + v.w;
    float ss = v.x * v.x + v.y * v.y + v.z * v.z + v.w * v.w;
#pragma unroll
    for (int o = 16; o > 0; o >>= 1) {
        s  += __shfl_xor_sync(0xffffffffu, s, o);
        ss += __shfl_xor_sync(0xffffffffu, ss, o);
    }
    if (lane == 0) { r1[wrp] = s; r2[wrp] = ss; }
    __syncthreads();
    if (wrp == 0) {
        float a = (lane < 8) ? r1[lane] : 0.f;
        float c2 = (lane < 8) ? r2[lane] : 0.f;
#pragma unroll
        for (int o = 4; o > 0; o >>= 1) {
            a  += __shfl_xor_sync(0xffffffffu, a, o);
            c2 += __shfl_xor_sync(0xffffffffu, c2, o);
        }
        if (lane == 0) { r1[0] = a; r2[0] = c2; }
    }
    __syncthreads();
    float mu = r1[0] * (1.0f / DD);
    float var = r2[0] * (1.0f / DD) - mu * mu;
    float rstd = rsqrtf(var + LN_EPS);
    float4 wv = ((const float4*)w)[tid];
    float4 sh = ((const float4*)(mod + (size_t)b * MODW + shiftSeg * DD))[tid];
    float4 sc = ((const float4*)(mod + (size_t)b * MODW + scaleSeg * DD))[tid];
    float y0 = fmaf((v.x - mu) * rstd * wv.x, 1.0f + sc.x, sh.x);
    float y1 = fmaf((v.y - mu) * rstd * wv.y, 1.0f + sc.y, sh.y);
    float y2 = fmaf((v.z - mu) * rstd * wv.z, 1.0f + sc.z, sh.z);
    float y3 = fmaf((v.w - mu) * rstd * wv.w, 1.0f + sc.w, sh.w);
    uint2 o2 = make_uint2(f2bf(y0, y1), f2bf(y2, y3));
    *(uint2*)(out + (size_t)row * DD + tid * 4) = o2;
}

__device__ __forceinline__ float gelu_tanh(float x) {
    float x3 = x * x * x;
    return 0.5f * x * (1.0f + tanhf(0.7978845608028654f * (x + 0.044715f * x3)));
}

// ---------------- bf16 tensor-core GEMM: persistent tiles ---------------------
#define TG_STRIDE 40
#define TG_HBUF (128 * TG_STRIDE)
#define TG_STAGE (2 * TG_HBUF)
#define TG_BYTES (4 * TG_STAGE * 2)              // 81920 B

template<int EPI>
__global__ __launch_bounds__(128, 2)
void tgemm(const bf16* __restrict__ A, const bf16* __restrict__ Bt,
           const float* __restrict__ bias, const float* __restrict__ resid,
           const float* __restrict__ mod, int modOff,
           const float* __restrict__ cosb, const float* __restrict__ sinb,
           void* __restrict__ Cv, int M, int N, int K) {
    extern __shared__ bf16 smh[];
    const int tid = threadIdx.x;
    const int lane = tid & 31, wid = tid >> 5;
    const int gid = lane >> 2, tig = lane & 3;
    const int m0w = (wid & 1) * 64;
    const int n0w = (wid >> 1) * 64;
    const int aRowOff = (lane & 15) * TG_STRIDE + 8 * (lane >> 4);
    const int bRowOff = (lane & 7) * TG_STRIDE + 8 * ((lane >> 3) & 1);
    const int NS = K >> 5;
    const int ntx = N >> 7;
    const int totalTiles = (M >> 7) * ntx;

    for (int tile = blockIdx.x; tile < totalTiles; tile += gridDim.x) {
        const int bx = tile % ntx, by = tile / ntx;
        const bf16* Ag = A + (size_t)(by * 128) * K;
        const bf16* Bg = Bt + (size_t)(bx * 128) * K;

        float acc[4][8][4];
#pragma unroll
        for (int i = 0; i < 4; i++)
#pragma unroll
            for (int j = 0; j < 8; j++)
#pragma unroll
                for (int r = 0; r < 4; r++) acc[i][j][r] = 0.f;

        auto issue = [&](int ks) {
            bf16* As = smh + (ks & 3) * TG_STAGE;
            bf16* Bs = As + TG_HBUF;
#pragma unroll
            for (int e = 0; e < 4; e++) {
                int idx = tid + e * 128;
                int row = idx >> 2, q = idx & 3;
                cp16(&As[row * TG_STRIDE + q * 8], Ag + (size_t)row * K + ks * 32 + q * 8);
            }
#pragma unroll
            for (int e = 0; e < 4; e++) {
                int idx = tid + e * 128;
                int row = idx >> 2, q = idx & 3;
                cp16(&Bs[row * TG_STRIDE + q * 8], Bg + (size_t)row * K + ks * 32 + q * 8);
            }
            asm volatile("cp.async.commit_group;");
        };

        issue(0); issue(1); issue(2);

        for (int ks = 0; ks < NS; ks++) {
            if (ks + 2 < NS) asm volatile("cp.async.wait_group 2;" ::: "memory");
            else             asm volatile("cp.async.wait_group 0;" ::: "memory");
            __syncthreads();
            if (ks + 3 < NS) issue(ks + 3);
            const bf16* As = smh + (ks & 3) * TG_STAGE;
            const bf16* Bs = As + TG_HBUF;

            unsigned afA[4][4], bfA[8][2], afB[4][4], bfB[8][2];
#pragma unroll
            for (int mt = 0; mt < 4; mt++)
                ldsm_x4(afA[mt][0], afA[mt][1], afA[mt][2], afA[mt][3],
                        smaddr(&As[(m0w + mt * 16) * TG_STRIDE + aRowOff]));
#pragma unroll
            for (int nt = 0; nt < 8; nt++)
                ldsm_x2(bfA[nt][0], bfA[nt][1],
                        smaddr(&Bs[(n0w + nt * 8) * TG_STRIDE + bRowOff]));
#pragma unroll
            for (int mt = 0; mt < 4; mt++)
                ldsm_x4(afB[mt][0], afB[mt][1], afB[mt][2], afB[mt][3],
                        smaddr(&As[(m0w + mt * 16) * TG_STRIDE + aRowOff + 16]));
#pragma unroll
            for (int nt = 0; nt < 8; nt++)
                ldsm_x2(bfB[nt][0], bfB[nt][1],
                        smaddr(&Bs[(n0w + nt * 8) * TG_STRIDE + bRowOff + 16]));

#pragma unroll
            for (int mt = 0; mt < 4; mt++)
#pragma unroll
                for (int nt = 0; nt < 8; nt++)
                    mma_bf16(acc[mt][nt], afA[mt][0], afA[mt][1], afA[mt][2], afA[mt][3],
                             bfA[nt][0], bfA[nt][1]);
#pragma unroll
            for (int mt = 0; mt < 4; mt++)
#pragma unroll
                for (int nt = 0; nt < 8; nt++)
                    mma_bf16(acc[mt][nt], afB[mt][0], afB[mt][1], afB[mt][2], afB[mt][3],
                             bfB[nt][0], bfB[nt][1]);
        }
        __syncthreads();   // all smem reads done before next tile's prologue

        // ---- epilogue ----
        if (EPI == 4) {
            int colBase = bx * 128 + n0w;          // warp-uniform, 64-aligned
            int sel = colBase >> 10;               // 0=q, 1=k, 2=v
            bf16* C = (bf16*)Cv;
            if (sel == 2) {
#pragma unroll
                for (int mt = 0; mt < 4; mt++)
#pragma unroll
                    for (int half = 0; half < 2; half++) {
                        int row = by * 128 + m0w + mt * 16 + gid + 8 * half;
                        size_t rowBase = (size_t)row * N;
#pragma unroll
                        for (int nt = 0; nt < 8; nt++) {
                            int col = colBase + nt * 8 + 2 * tig;
                            *(unsigned*)&C[rowBase + col] =
                                f2bf(acc[mt][nt][2 * half], acc[mt][nt][2 * half + 1]);
                        }
                    }
            } else {
                float scale = sel ? 1.0f : 0.125f;
#pragma unroll
                for (int mt = 0; mt < 4; mt++)
#pragma unroll
                    for (int half = 0; half < 2; half++) {
                        int row = by * 128 + m0w + mt * 16 + gid + 8 * half;
                        int s = row & (SS - 1);
                        size_t rowBase = (size_t)row * N;
#pragma unroll
                        for (int nt = 0; nt < 4; nt++) {
                            int e0 = nt * 8 + 2 * tig;
                            float c0 = cosb[s * 32 + e0], c1 = cosb[s * 32 + e0 + 1];
                            float sv0 = sinb[s * 32 + e0], sv1 = sinb[s * 32 + e0 + 1];
                            float t1a = acc[mt][nt][2 * half];
                            float t1b = acc[mt][nt][2 * half + 1];
                            float t2a = acc[mt][nt + 4][2 * half];
                            float t2b = acc[mt][nt + 4][2 * half + 1];
                            int col = colBase + e0;
                            *(unsigned*)&C[rowBase + col] =
                                f2bf((t1a * c0 - t2a * sv0) * scale,
                                     (t1b * c1 - t2b * sv1) * scale);
                            *(unsigned*)&C[rowBase + col + 32] =
                                f2bf((t2a * c0 + t1a * sv0) * scale,
                                     (t2b * c1 + t1b * sv1) * scale);
                        }
                    }
            }
        } else {
#pragma unroll
            for (int mt = 0; mt < 4; mt++) {
#pragma unroll
                for (int half = 0; half < 2; half++) {
                    int row = by * 128 + m0w + mt * 16 + gid + 8 * half;
                    size_t rowBase = (size_t)row * N;
#pragma unroll
                    for (int nt = 0; nt < 8; nt++) {
                        int col = bx * 128 + n0w + nt * 8 + 2 * tig;
                        float v0 = acc[mt][nt][2 * half];
                        float v1 = acc[mt][nt][2 * half + 1];
                        if (EPI == 1) {
                            v0 = gelu_tanh(v0 + bias[col]);
                            v1 = gelu_tanh(v1 + bias[col + 1]);
                            *(unsigned*)&((bf16*)Cv)[rowBase + col] = f2bf(v0, v1);
                        } else if (EPI == 2) {
                            if (bias) { v0 += bias[col]; v1 += bias[col + 1]; }
                            size_t mb = (size_t)(row >> 10) * MODW + modOff + col;
                            float g0 = mod[mb], g1 = mod[mb + 1];
                            float2 rr = *(const float2*)&resid[rowBase + col];
                            *(float2*)&((float*)Cv)[rowBase + col] =
                                make_float2(fmaf(g0, v0, rr.x), fmaf(g1, v1, rr.y));
                        } else {
                            *(unsigned*)&((bf16*)Cv)[rowBase + col] = f2bf(v0, v1);
                        }
                    }
                }
            }
        }
    }
}

// ---------------- attention: flash, register-resident P, ldmatrix.trans V -----
#define AT_STRIDE 72
#define AT_HBUF (64 * AT_STRIDE)
#define AT_SMEM_BYTES (5 * AT_HBUF * 2)          // 46080 B (no Ps buffer)

__global__ __launch_bounds__(128, 3)
void attn_mma_kernel(const bf16* __restrict__ qkv, bf16* __restrict__ out) {
    extern __shared__ bf16 smh[];
    bf16* Qs = smh;
    bf16* Kb[2] = { Qs + AT_HBUF, Qs + 3 * AT_HBUF };
    bf16* Vb[2] = { Qs + 2 * AT_HBUF, Qs + 4 * AT_HBUF };
    int bh = blockIdx.x;
    int b = bh >> 4, h = bh & 15;
    size_t bS = (size_t)b * SS;
    int q0 = blockIdx.y * 64;
    int tid = threadIdx.x, w = tid >> 5, lane = tid & 31;
    int gid = lane >> 2, tig = lane & 3;
    const int aRowOff = (lane & 15) * AT_STRIDE + 8 * (lane >> 4);
    const int bRowOff = (lane & 7) * AT_STRIDE + 8 * ((lane >> 3) & 1);
    const int vRowOff = (lane & 7) + 8 * ((lane >> 3) & 1);

    auto issue_tile = [&](int kt) {
        int kb0 = kt * 64;
        bf16* Ks = Kb[kt & 1];
        bf16* Vs = Vb[kt & 1];
#pragma unroll
        for (int e = 0; e < 4; e++) {
            int idx = tid + e * 128;
            int r = idx >> 3, q = idx & 7;
            cp16(&Ks[r * AT_STRIDE + q * 8],
                 qkv + (bS + kb0 + r) * 3072 + 1024 + h * 64 + q * 8);
            cp16(&Vs[r * AT_STRIDE + q * 8],
                 qkv + (bS + kb0 + r) * 3072 + 2048 + h * 64 + q * 8);
        }
        asm volatile("cp.async.commit_group;");
    };

    issue_tile(0);

    {
        int q = tid >> 1, d0 = (tid & 1) * 32;
        const uint4* src = (const uint4*)(qkv + (bS + q0 + q) * 3072 + h * 64 + d0);
        uint4* dst = (uint4*)&Qs[q * AT_STRIDE + d0];
        dst[0] = src[0];
        dst[1] = src[1];
        dst[2] = src[2];
        dst[3] = src[3];
    }
    __syncthreads();

    unsigned qf[4][4];
#pragma unroll
    for (int kb4 = 0; kb4 < 4; kb4++)
        ldsm_x4(qf[kb4][0], qf[kb4][1], qf[kb4][2], qf[kb4][3],
                smaddr(&Qs[(w * 16) * AT_STRIDE + aRowOff + kb4 * 16]));

    float o[8][4];
#pragma unroll
    for (int nt = 0; nt < 8; nt++)
#pragma unroll
        for (int r = 0; r < 4; r++) o[nt][r] = 0.f;
    float mA = -1e30f, mB = -1e30f, lA = 0.f, lB = 0.f;

    for (int kt = 0; kt < 16; kt++) {
        asm volatile("cp.async.wait_group 0;" ::: "memory");
        __syncthreads();
        if (kt + 1 < 16) issue_tile(kt + 1);
        const bf16* Ks = Kb[kt & 1];
        const bf16* Vs = Vb[kt & 1];

        // ---- QK^T ----
        float s[8][4];
#pragma unroll
        for (int nt = 0; nt < 8; nt++)
#pragma unroll
            for (int r = 0; r < 4; r++) s[nt][r] = 0.f;
#pragma unroll
        for (int kb4 = 0; kb4 < 4; kb4++) {
#pragma unroll
            for (int nt = 0; nt < 8; nt++) {
                unsigned b0, b1;
                ldsm_x2(b0, b1, smaddr(&Ks[(nt * 8) * AT_STRIDE + bRowOff + kb4 * 16]));
                mma_bf16(s[nt], qf[kb4][0], qf[kb4][1], qf[kb4][2], qf[kb4][3], b0, b1);
            }
        }

        // ---- online softmax (rows gid, gid+8) ----
        float tmA = -1e30f, tmB = -1e30f;
#pragma unroll
        for (int nt = 0; nt < 8; nt++) {
            tmA = fmaxf(tmA, fmaxf(s[nt][0], s[nt][1]));
            tmB = fmaxf(tmB, fmaxf(s[nt][2], s[nt][3]));
        }
        tmA = fmaxf(tmA, __shfl_xor_sync(0xffffffffu, tmA, 1));
        tmA = fmaxf(tmA, __shfl_xor_sync(0xffffffffu, tmA, 2));
        tmB = fmaxf(tmB, __shfl_xor_sync(0xffffffffu, tmB, 1));
        tmB = fmaxf(tmB, __shfl_xor_sync(0xffffffffu, tmB, 2));
        float nmA = fmaxf(mA, tmA), nmB = fmaxf(mB, tmB);
        float corrA = __expf(mA - nmA), corrB = __expf(mB - nmB);
        mA = nmA; mB = nmB;
        float sumA = 0.f, sumB = 0.f;
#pragma unroll
        for (int nt = 0; nt < 8; nt++) {
            s[nt][0] = __expf(s[nt][0] - nmA);
            s[nt][1] = __expf(s[nt][1] - nmA);
            s[nt][2] = __expf(s[nt][2] - nmB);
            s[nt][3] = __expf(s[nt][3] - nmB);
            sumA += s[nt][0] + s[nt][1];
            sumB += s[nt][2] + s[nt][3];
        }
        sumA += __shfl_xor_sync(0xffffffffu, sumA, 1);
        sumA += __shfl_xor_sync(0xffffffffu, sumA, 2);
        sumB += __shfl_xor_sync(0xffffffffu, sumB, 1);
        sumB += __shfl_xor_sync(0xffffffffu, sumB, 2);
        lA = lA * corrA + sumA;
        lB = lB * corrB + sumB;
#pragma unroll
        for (int nt = 0; nt < 8; nt++) {
            o[nt][0] *= corrA; o[nt][1] *= corrA;
            o[nt][2] *= corrB; o[nt][3] *= corrB;
        }

        // ---- PV: P directly from registers (A-fragment == S-fragment layout) --
#pragma unroll
        for (int kc = 0; kc < 4; kc++) {
            unsigned pf0 = f2bf(s[2 * kc][0],     s[2 * kc][1]);
            unsigned pf1 = f2bf(s[2 * kc][2],     s[2 * kc][3]);
            unsigned pf2 = f2bf(s[2 * kc + 1][0], s[2 * kc + 1][1]);
            unsigned pf3 = f2bf(s[2 * kc + 1][2], s[2 * kc + 1][3]);
#pragma unroll
            for (int nt = 0; nt < 8; nt++) {
                unsigned b0, b1;
                ldsm_x2t(b0, b1,
                         smaddr(&Vs[(kc * 16 + vRowOff) * AT_STRIDE + nt * 8]));
                mma_bf16(o[nt], pf0, pf1, pf2, pf3, b0, b1);
            }
        }
    }

    float invA = 1.0f / lA, invB = 1.0f / lB;
    size_t rowA = (bS + q0 + w * 16 + gid) * 1024 + h * 64;
    size_t rowB = (bS + q0 + w * 16 + gid + 8) * 1024 + h * 64;
#pragma unroll
    for (int nt = 0; nt < 8; nt++) {
        int col = nt * 8 + 2 * tig;
        *(unsigned*)&out[rowA + col] = f2bf(o[nt][0] * invA, o[nt][1] * invA);
        *(unsigned*)&out[rowB + col] = f2bf(o[nt][2] * invB, o[nt][3] * invB);
    }
}

// ---------------- launch ----------------
extern "C" void kernel_launch(void* const* d_in, const int* in_sizes, int n_in,
                              void* d_out, int out_size) {
    const float* x       = (const float*)d_in[0];
    const float* c       = (const float*)d_in[1];
    const float* norm1_w = (const float*)d_in[2];
    const float* norm2_w = (const float*)d_in[3];
    const float* w_qkv   = (const float*)d_in[4];
    const float* w_out   = (const float*)d_in[5];
    const float* w1      = (const float*)d_in[6];
    const float* b1      = (const float*)d_in[7];
    const float* w2      = (const float*)d_in[8];
    const float* b2      = (const float*)d_in[9];
    const float* adaLN_w = (const float*)d_in[10];
    const float* adaLN_b = (const float*)d_in[11];
    const float* cosb    = (const float*)d_in[12];
    const float* sinb    = (const float*)d_in[13];
    float* out = (float*)d_out;

    float *mod, *x1;
    bf16 *xm, *qkv, *attn, *hbuf, *wqkv_t, *wout_t, *w1_t, *w2_t;
    cudaGetSymbolAddress((void**)&mod,  g_mod);
    cudaGetSymbolAddress((void**)&xm,   g_xm);
    cudaGetSymbolAddress((void**)&qkv,  g_qkv);
    cudaGetSymbolAddress((void**)&attn, g_attn);
    cudaGetSymbolAddress((void**)&x1,   g_x1);
    cudaGetSymbolAddress((void**)&hbuf, g_h);
    cudaGetSymbolAddress((void**)&wqkv_t, g_wqkv_t);
    cudaGetSymbolAddress((void**)&wout_t, g_wout_t);
    cudaGetSymbolAddress((void**)&w1_t,   g_w1_t);
    cudaGetSymbolAddress((void**)&w2_t,   g_w2_t);

    cudaFuncSetAttribute(attn_mma_kernel, cudaFuncAttributeMaxDynamicSharedMemorySize,
                         AT_SMEM_BYTES);
    cudaFuncSetAttribute(tgemm<1>, cudaFuncAttributeMaxDynamicSharedMemorySize, TG_BYTES);
    cudaFuncSetAttribute(tgemm<2>, cudaFuncAttributeMaxDynamicSharedMemorySize, TG_BYTES);
    cudaFuncSetAttribute(tgemm<4>, cudaFuncAttributeMaxDynamicSharedMemorySize, TG_BYTES);

    const int PERSIST = 296;   // 148 SMs x 2 CTAs

    // 0) weights -> bf16 [N][K] transpose + adaLN mod vector (single launch)
    wtrans_all_kernel<<<3168, 256>>>(w_qkv, w_out, w1, w2,
                                     wqkv_t, wout_t, w1_t, w2_t,
                                     c, adaLN_w, adaLN_b, mod);

    // 1) LN1 + modulate
    ln_mod_kernel<<<BB * SS, 256>>>(x, norm1_w, mod, 0, 1, xm);

    // 2) QKV GEMM with fused RoPE -> bf16 qkv  (768 tiles, persistent)
    tgemm<4><<<PERSIST, 128, TG_BYTES>>>(
        xm, wqkv_t, nullptr, nullptr, nullptr, 0, cosb, sinb, qkv, BB * SS, 3 * DD, DD);

    // 3) attention (register P, trans V) -> bf16 attn
    attn_mma_kernel<<<dim3(BB * HH, SS / 64), 128, AT_SMEM_BYTES>>>(qkv, attn);

    // 4) out-proj + gated residual -> fp32 x1  (256 tiles)
    tgemm<2><<<256, 128, TG_BYTES>>>(
        attn, wout_t, nullptr, x, mod, 2 * DD, nullptr, nullptr, x1, BB * SS, DD, DD);

    // 5) LN2 + modulate
    ln_mod_kernel<<<BB * SS, 256>>>(x1, norm2_w, mod, 3, 4, xm);

    // 6) MLP up + GELU -> bf16 h  (1024 tiles, persistent)
    tgemm<1><<<PERSIST, 128, TG_BYTES>>>(
        xm, w1_t, b1, nullptr, nullptr, 0, nullptr, nullptr, hbuf, BB * SS, MLPD, DD);

    // 7) MLP down + gated residual -> fp32 out  (256 tiles)
    tgemm<2><<<256, 128, TG_BYTES>>>(
        hbuf, w2_t, b2, x1, mod, 5 * DD, nullptr, nullptr, out, BB * SS, DD, MLPD);
}